// round 1
// baseline (speedup 1.0000x reference)
#include <cuda_runtime.h>

#define EPS 1e-3f

static constexpr int MROWS = 8192;   // B*H*W
static constexpr int CCH   = 512;
static constexpr int CH2   = 256;

// ---------------- scratch (device globals; no allocs allowed) ----------------
__device__ __align__(16) float g_agg[MROWS * CCH];
__device__ __align__(16) float g_uv [MROWS * CH2];
__device__ __align__(16) float g_A  [MROWS * CH2];
__device__ __align__(16) float g_Pv [MROWS * CH2];
__device__ __align__(16) float g_Ph [MROWS * CH2];
__device__ __align__(16) float g_upd[MROWS * CH2];

__device__ __align__(16) float g_s2[CH2], g_t2[CH2], g_s3[CH2], g_t3[CH2];
__device__ __align__(16) float g_s5[CCH], g_t5[CCH];
__device__ float g_wa[4], g_wr[4], g_ca, g_cr;

// ---------------- packed f32x2 helpers (Blackwell 2x fp32) ----------------
__device__ __forceinline__ unsigned long long fma2(unsigned long long a,
                                                   unsigned long long b,
                                                   unsigned long long c) {
    unsigned long long d;
    asm("fma.rn.f32x2 %0, %1, %2, %3;" : "=l"(d) : "l"(a), "l"(b), "l"(c));
    return d;
}
__device__ __forceinline__ unsigned long long pack2(float x) {
    unsigned long long d;
    unsigned u = __float_as_uint(x);
    asm("mov.b64 %0, {%1, %2};" : "=l"(d) : "r"(u), "r"(u));
    return d;
}
__device__ __forceinline__ float2 unpack2(unsigned long long v) {
    unsigned lo, hi;
    asm("mov.b64 {%0, %1}, %2;" : "=r"(lo), "=r"(hi) : "l"(v));
    return make_float2(__uint_as_float(lo), __uint_as_float(hi));
}

// ---------------- param folding ----------------
__global__ void fold_k(const float* w_ea, const float* b_ea,
                       const float* g1, const float* b1, const float* m1, const float* v1,
                       const float* b_vu,
                       const float* g2, const float* b2, const float* m2, const float* v2,
                       const float* b_eu,
                       const float* g3, const float* b3, const float* m3, const float* v3,
                       const float* w_er, const float* b_er,
                       const float* g4, const float* b4, const float* m4, const float* v4,
                       const float* g5, const float* b5, const float* m5, const float* v5) {
    int d = threadIdx.x;
    if (d < CH2) {
        float s2 = g2[d] * rsqrtf(v2[d] + EPS);
        g_s2[d] = s2;
        g_t2[d] = (b_vu[d] - m2[d]) * s2 + b2[d];
        float s3 = g3[d] * rsqrtf(v3[d] + EPS);
        g_s3[d] = s3;
        g_t3[d] = (b_eu[d] - m3[d]) * s3 + b3[d];
    }
    if (d < CCH) {
        float s5 = g5[d] * rsqrtf(v5[d] + EPS);
        g_s5[d] = s5;
        g_t5[d] = b5[d] - m5[d] * s5;
    }
    if (d == 0) {
        float s1 = g1[0] * rsqrtf(v1[0] + EPS);
        #pragma unroll
        for (int n = 0; n < 4; n++) g_wa[n] = w_ea[n] * s1;
        g_ca = (b_ea[0] - m1[0]) * s1 + b1[0];
        float s4 = g4[0] * rsqrtf(v4[0] + EPS);
        #pragma unroll
        for (int n = 0; n < 4; n++) g_wr[n] = w_er[n] * s4;
        g_cr = (b_er[0] - m4[0]) * s4 + b4[0];
    }
}

// ---------------- edge aggregation (elementwise) ----------------
// agg[p,c] = relu( x[p,c] * (wa0*x[up] + wa1*x[down] + wa2*x[left] + wa3*x[right]) + ca )
__global__ void agg_k(const float* __restrict__ X) {
    int idx = blockIdx.x * 256 + threadIdx.x;       // over 8192*128 float4s
    int p = idx >> 7;
    int c = (idx & 127) << 2;
    int h = (p >> 6) & 63, w = p & 63;
    int baseH = p & ~4032;                           // 4032 = 63<<6
    int pu = baseH | (((h + 63) & 63) << 6);
    int pd = baseH | (((h + 1) & 63) << 6);
    int baseW = p & ~63;
    int pl = baseW | ((w + 63) & 63);
    int pr = baseW | ((w + 1) & 63);
    float4 xv = *(const float4*)(X + p  * 512 + c);
    float4 xu = *(const float4*)(X + pu * 512 + c);
    float4 xd = *(const float4*)(X + pd * 512 + c);
    float4 xl = *(const float4*)(X + pl * 512 + c);
    float4 xr = *(const float4*)(X + pr * 512 + c);
    float w0 = g_wa[0], w1 = g_wa[1], w2 = g_wa[2], w3 = g_wa[3], ca = g_ca;
    float4 o;
    o.x = fmaxf(fmaf(xv.x, w0 * xu.x + w1 * xd.x + w2 * xl.x + w3 * xr.x, ca), 0.f);
    o.y = fmaxf(fmaf(xv.y, w0 * xu.y + w1 * xd.y + w2 * xl.y + w3 * xr.y, ca), 0.f);
    o.z = fmaxf(fmaf(xv.z, w0 * xu.z + w1 * xd.z + w2 * xl.z + w3 * xr.z, ca), 0.f);
    o.w = fmaxf(fmaf(xv.w, w0 * xu.w + w1 * xd.w + w2 * xl.w + w3 * xr.w, ca), 0.f);
    *(float4*)(g_agg + p * 512 + c) = o;
}

// ---------------- GEMM (f32x2 SIMT, 64x128 tile, 256 threads) ----------------
// MODE 0: uv = relu(s2*([x|agg] @ w_vu) + t2)      K=1024 N=256  -> g_uv
// MODE 1: z=0: A = x@Wv ; z=1: Pv=(x.*x_up)@We ; z=2: Ph=(x.*x_left)@We  (raw)
// MODE 2: out = relu(s5*([x|upd] @ w_fc) + t5)     K=768  N=512  -> d_out
template<int MODE>
__global__ __launch_bounds__(256) void gemm_k(const float* __restrict__ X,
                                              const float* __restrict__ B0,
                                              float* __restrict__ OutExt) {
    constexpr int K = (MODE == 0) ? 1024 : ((MODE == 1) ? 512 : 768);
    constexpr int N = (MODE == 2) ? 512 : 256;
    constexpr int BM = 64, BN = 128, BK = 16;
    constexpr int T = K / BK;

    const int tid = threadIdx.x;
    const int m0 = blockIdx.y * BM;
    const int n0 = blockIdx.x * BN;

    const float* Bm = B0;
    float* Out;
    if (MODE == 0)      Out = g_uv;
    else if (MODE == 2) Out = OutExt;
    else {
        int z = blockIdx.z;
        if (z == 0)      { Out = g_A; }
        else if (z == 1) { Out = g_Pv; Bm = B0 + 512 * 256; }
        else             { Out = g_Ph; Bm = B0 + 512 * 256; }
    }

    __shared__ float As[BK][BM + 4];
    __shared__ float Bs[BK][BN];

    // A-tile loader coords: 1 float4 per thread (64 rows x 16 k)
    const int am  = tid >> 2;          // 0..63
    const int akv = (tid & 3) << 2;    // 0,4,8,12
    const int arow = m0 + am;
    int arow2 = arow;                  // neighbor row for MODE 1 products
    if (MODE == 1) {
        int z = blockIdx.z;
        int h = (arow >> 6) & 63, w = arow & 63;
        if (z == 1)      arow2 = (arow & ~4032) | (((h + 63) & 63) << 6);  // up (h-1)
        else if (z == 2) arow2 = (arow & ~63)   | ((w + 63) & 63);         // left (w-1)
    }
    // B-tile loader coords: 2 float4 per thread (16 k x 128 n)
    const int bk0 = tid >> 5;          // 0..7 (second load: +8)
    const int bnv = (tid & 31) << 2;

    const int tx = tid & 15;           // col group: 8 cols each
    const int ty = tid >> 4;           // row group: 4 rows each

    unsigned long long acc[4][4];
    #pragma unroll
    for (int i = 0; i < 4; i++)
        #pragma unroll
        for (int j = 0; j < 4; j++) acc[i][j] = 0ull;

    auto ldA = [&](int k0) -> float4 {
        int gk = k0 + akv;
        float4 v;
        if (MODE == 0) {
            const float* s = (gk < 512) ? (X + arow * 512 + gk)
                                        : (g_agg + arow * 512 + (gk - 512));
            v = *(const float4*)s;
        } else if (MODE == 2) {
            const float* s = (gk < 512) ? (X + arow * 512 + gk)
                                        : (g_upd + arow * 256 + (gk - 512));
            v = *(const float4*)s;
        } else {
            v = *(const float4*)(X + arow * 512 + gk);
            if (blockIdx.z != 0) {
                float4 u = *(const float4*)(X + arow2 * 512 + gk);
                v.x *= u.x; v.y *= u.y; v.z *= u.z; v.w *= u.w;
            }
        }
        return v;
    };
    auto ldB0 = [&](int k0) -> float4 {
        return *(const float4*)(Bm + (k0 + bk0) * N + n0 + bnv);
    };
    auto ldB1 = [&](int k0) -> float4 {
        return *(const float4*)(Bm + (k0 + bk0 + 8) * N + n0 + bnv);
    };
    auto stAB = [&](float4 a, float4 b0, float4 b1) {
        As[akv + 0][am] = a.x; As[akv + 1][am] = a.y;
        As[akv + 2][am] = a.z; As[akv + 3][am] = a.w;
        *(float4*)&Bs[bk0][bnv]     = b0;
        *(float4*)&Bs[bk0 + 8][bnv] = b1;
    };

    // prologue
    {
        float4 a = ldA(0), b0 = ldB0(0), b1 = ldB1(0);
        stAB(a, b0, b1);
    }
    __syncthreads();

    #pragma unroll 1
    for (int t = 0; t < T; t++) {
        float4 aN, bN0, bN1;
        if (t + 1 < T) {
            int k0 = (t + 1) * BK;
            aN = ldA(k0); bN0 = ldB0(k0); bN1 = ldB1(k0);
        }
        #pragma unroll
        for (int k = 0; k < BK; k++) {
            float4 a = *(const float4*)&As[k][ty * 4];
            ulonglong2 q0 = *(const ulonglong2*)&Bs[k][tx * 8];
            ulonglong2 q1 = *(const ulonglong2*)&Bs[k][tx * 8 + 4];
            float av[4] = {a.x, a.y, a.z, a.w};
            #pragma unroll
            for (int i = 0; i < 4; i++) {
                unsigned long long ap = pack2(av[i]);
                acc[i][0] = fma2(ap, q0.x, acc[i][0]);
                acc[i][1] = fma2(ap, q0.y, acc[i][1]);
                acc[i][2] = fma2(ap, q1.x, acc[i][2]);
                acc[i][3] = fma2(ap, q1.y, acc[i][3]);
            }
        }
        if (t + 1 < T) {
            __syncthreads();
            stAB(aN, bN0, bN1);
            __syncthreads();
        }
    }

    // epilogue
    const int row0 = m0 + ty * 4;
    const int col0 = n0 + tx * 8;
    #pragma unroll
    for (int i = 0; i < 4; i++) {
        float* orow = Out + (row0 + i) * N + col0;
        #pragma unroll
        for (int jp = 0; jp < 4; jp++) {
            float2 v = unpack2(acc[i][jp]);
            if (MODE == 1) {
                *(float2*)(orow + jp * 2) = v;
            } else {
                const float* sc = (MODE == 0) ? g_s2 : g_s5;
                const float* sh = (MODE == 0) ? g_t2 : g_t5;
                int cidx = col0 + jp * 2;
                v.x = fmaxf(fmaf(v.x, sc[cidx],     sh[cidx]),     0.f);
                v.y = fmaxf(fmaf(v.y, sc[cidx + 1], sh[cidx + 1]), 0.f);
                *(float2*)(orow + jp * 2) = v;
            }
        }
    }
}

// ---------------- edge reduce + vertex*edge product (elementwise) ----------------
// ue_n = relu(s3*(A + E_n) + t3); ur = relu(sum_n wr_n*ue_n + cr); upd = uv*ur
// E0 = Pv[p], E1 = Pv[p_down], E2 = Ph[p], E3 = Ph[p_right]
__global__ void ur_k() {
    int idx = blockIdx.x * 256 + threadIdx.x;        // over 8192*64 float4s
    int p = idx >> 6;
    int d = (idx & 63) << 2;
    int h = (p >> 6) & 63, w = p & 63;
    int pdn = (p & ~4032) | (((h + 1) & 63) << 6);
    int prt = (p & ~63)   | ((w + 1) & 63);
    const float4 A  = *(const float4*)(g_A  + p   * 256 + d);
    const float4 e0 = *(const float4*)(g_Pv + p   * 256 + d);
    const float4 e1 = *(const float4*)(g_Pv + pdn * 256 + d);
    const float4 e2 = *(const float4*)(g_Ph + p   * 256 + d);
    const float4 e3 = *(const float4*)(g_Ph + prt * 256 + d);
    const float4 s3 = *(const float4*)(g_s3 + d);
    const float4 t3 = *(const float4*)(g_t3 + d);
    const float4 uv = *(const float4*)(g_uv + p * 256 + d);
    float w0 = g_wr[0], w1 = g_wr[1], w2 = g_wr[2], w3 = g_wr[3], cr = g_cr;
    float4 o;
#define UR_COMP(f)                                                      \
    {                                                                   \
        float u0 = fmaxf(fmaf(A.f + e0.f, s3.f, t3.f), 0.f);            \
        float u1 = fmaxf(fmaf(A.f + e1.f, s3.f, t3.f), 0.f);            \
        float u2 = fmaxf(fmaf(A.f + e2.f, s3.f, t3.f), 0.f);            \
        float u3 = fmaxf(fmaf(A.f + e3.f, s3.f, t3.f), 0.f);            \
        float r  = fmaxf(w0*u0 + w1*u1 + w2*u2 + w3*u3 + cr, 0.f);      \
        o.f = uv.f * r;                                                 \
    }
    UR_COMP(x) UR_COMP(y) UR_COMP(z) UR_COMP(w)
#undef UR_COMP
    *(float4*)(g_upd + p * 256 + d) = o;
}

// ---------------- launch ----------------
extern "C" void kernel_launch(void* const* d_in, const int* in_sizes, int n_in,
                              void* d_out, int out_size) {
    const float* x    = (const float*)d_in[0];
    const float* w_ea = (const float*)d_in[1];
    const float* b_ea = (const float*)d_in[2];
    const float* g1   = (const float*)d_in[3];
    const float* b1   = (const float*)d_in[4];
    const float* m1   = (const float*)d_in[5];
    const float* v1   = (const float*)d_in[6];
    const float* w_vu = (const float*)d_in[7];
    const float* b_vu = (const float*)d_in[8];
    const float* g2   = (const float*)d_in[9];
    const float* b2   = (const float*)d_in[10];
    const float* m2   = (const float*)d_in[11];
    const float* v2   = (const float*)d_in[12];
    const float* w_eu = (const float*)d_in[13];
    const float* b_eu = (const float*)d_in[14];
    const float* g3   = (const float*)d_in[15];
    const float* b3   = (const float*)d_in[16];
    const float* m3   = (const float*)d_in[17];
    const float* v3   = (const float*)d_in[18];
    const float* w_er = (const float*)d_in[19];
    const float* b_er = (const float*)d_in[20];
    const float* g4   = (const float*)d_in[21];
    const float* b4   = (const float*)d_in[22];
    const float* m4   = (const float*)d_in[23];
    const float* v4   = (const float*)d_in[24];
    const float* w_fc = (const float*)d_in[25];
    const float* g5   = (const float*)d_in[26];
    const float* b5   = (const float*)d_in[27];
    const float* m5   = (const float*)d_in[28];
    const float* v5   = (const float*)d_in[29];

    fold_k<<<1, 512>>>(w_ea, b_ea, g1, b1, m1, v1,
                       b_vu, g2, b2, m2, v2,
                       b_eu, g3, b3, m3, v3,
                       w_er, b_er, g4, b4, m4, v4,
                       g5, b5, m5, v5);

    agg_k<<<4096, 256>>>(x);                                   // -> g_agg
    gemm_k<1><<<dim3(2, 128, 3), 256>>>(x, w_eu, nullptr);     // -> g_A, g_Pv, g_Ph
    gemm_k<0><<<dim3(2, 128), 256>>>(x, w_vu, nullptr);        // -> g_uv
    ur_k<<<2048, 256>>>();                                     // -> g_upd
    gemm_k<2><<<dim3(4, 128), 256>>>(x, w_fc, (float*)d_out);  // -> out
}

// round 4
// speedup vs baseline: 3.1260x; 3.1260x over previous
#include <cuda_runtime.h>
#include <cuda_bf16.h>
#include <cstdint>

#define EPS 1e-3f

static constexpr int MROWS = 8192;   // B*H*W
static constexpr int CCH   = 512;
static constexpr int CH2   = 256;

// ---------------- scratch (device globals; no allocs allowed) ----------------
// fp32 intermediates for the elementwise combine
__device__ __align__(16) float g_A  [MROWS * CH2];
__device__ __align__(16) float g_Pv [MROWS * CH2];
__device__ __align__(16) float g_Ph [MROWS * CH2];
__device__ __align__(16) float g_uv [MROWS * CH2];

// split-bf16 activation operands (hi/lo)
__device__ __align__(16) __nv_bfloat16 g_xs_hi[MROWS * CCH], g_xs_lo[MROWS * CCH];
__device__ __align__(16) __nv_bfloat16 g_pv_hi[MROWS * CCH], g_pv_lo[MROWS * CCH];
__device__ __align__(16) __nv_bfloat16 g_ph_hi[MROWS * CCH], g_ph_lo[MROWS * CCH];
__device__ __align__(16) __nv_bfloat16 g_ag_hi[MROWS * CCH], g_ag_lo[MROWS * CCH];
__device__ __align__(16) __nv_bfloat16 g_up_hi[MROWS * CH2], g_up_lo[MROWS * CH2];

// split-bf16 weights, transposed to [N][K] (k contiguous)
__device__ __align__(16) __nv_bfloat16 g_vuT_hi[256 * 1024], g_vuT_lo[256 * 1024];
__device__ __align__(16) __nv_bfloat16 g_wvT_hi[256 *  512], g_wvT_lo[256 *  512];
__device__ __align__(16) __nv_bfloat16 g_weT_hi[256 *  512], g_weT_lo[256 *  512];
__device__ __align__(16) __nv_bfloat16 g_fcT_hi[512 *  768], g_fcT_lo[512 *  768];

__device__ __align__(16) float g_s2[CH2], g_t2[CH2], g_s3[CH2], g_t3[CH2];
__device__ __align__(16) float g_s5[CCH], g_t5[CCH];
__device__ float g_wa[4], g_wr[4], g_ca, g_cr;

// ---------------- PTX helpers ----------------
__device__ __forceinline__ uint32_t s2u(const void* p) {
    uint32_t a;
    asm("{ .reg .u64 t; cvta.to.shared.u64 t, %1; cvt.u32.u64 %0, t; }" : "=r"(a) : "l"(p));
    return a;
}
__device__ __forceinline__ void cpasync16(uint32_t s, const void* g) {
    asm volatile("cp.async.cg.shared.global [%0], [%1], 16;" :: "r"(s), "l"(g));
}
#define CP_COMMIT() asm volatile("cp.async.commit_group;" ::: "memory")
#define CP_WAIT(n)  asm volatile("cp.async.wait_group %0;" :: "n"(n) : "memory")

__device__ __forceinline__ void ldsm4(uint32_t* r, uint32_t addr) {
    asm volatile("ldmatrix.sync.aligned.m8n8.x4.shared.b16 {%0,%1,%2,%3}, [%4];"
                 : "=r"(r[0]), "=r"(r[1]), "=r"(r[2]), "=r"(r[3]) : "r"(addr));
}
__device__ __forceinline__ void mma16816(float* d, const uint32_t* a, const uint32_t* b) {
    asm volatile(
        "mma.sync.aligned.m16n8k16.row.col.f32.bf16.bf16.f32 "
        "{%0,%1,%2,%3}, {%4,%5,%6,%7}, {%8,%9}, {%0,%1,%2,%3};"
        : "+f"(d[0]), "+f"(d[1]), "+f"(d[2]), "+f"(d[3])
        : "r"(a[0]), "r"(a[1]), "r"(a[2]), "r"(a[3]), "r"(b[0]), "r"(b[1]));
}

// split float4 -> packed bf16 hi/lo (2x uint2)
__device__ __forceinline__ void sp4(float4 v, uint2& h, uint2& l) {
    __nv_bfloat16 h0 = __float2bfloat16(v.x), h1 = __float2bfloat16(v.y);
    __nv_bfloat16 h2 = __float2bfloat16(v.z), h3 = __float2bfloat16(v.w);
    __nv_bfloat16 l0 = __float2bfloat16(v.x - __bfloat162float(h0));
    __nv_bfloat16 l1 = __float2bfloat16(v.y - __bfloat162float(h1));
    __nv_bfloat16 l2 = __float2bfloat16(v.z - __bfloat162float(h2));
    __nv_bfloat16 l3 = __float2bfloat16(v.w - __bfloat162float(h3));
    h.x = (uint32_t)__bfloat16_as_ushort(h0) | ((uint32_t)__bfloat16_as_ushort(h1) << 16);
    h.y = (uint32_t)__bfloat16_as_ushort(h2) | ((uint32_t)__bfloat16_as_ushort(h3) << 16);
    l.x = (uint32_t)__bfloat16_as_ushort(l0) | ((uint32_t)__bfloat16_as_ushort(l1) << 16);
    l.y = (uint32_t)__bfloat16_as_ushort(l2) | ((uint32_t)__bfloat16_as_ushort(l3) << 16);
}

// ---------------- param folding ----------------
__global__ void fold_k(const float* w_ea, const float* b_ea,
                       const float* g1, const float* b1, const float* m1, const float* v1,
                       const float* b_vu,
                       const float* g2, const float* b2, const float* m2, const float* v2,
                       const float* b_eu,
                       const float* g3, const float* b3, const float* m3, const float* v3,
                       const float* w_er, const float* b_er,
                       const float* g4, const float* b4, const float* m4, const float* v4,
                       const float* g5, const float* b5, const float* m5, const float* v5) {
    int d = threadIdx.x;
    if (d < CH2) {
        float s2 = g2[d] * rsqrtf(v2[d] + EPS);
        g_s2[d] = s2;
        g_t2[d] = (b_vu[d] - m2[d]) * s2 + b2[d];
        float s3 = g3[d] * rsqrtf(v3[d] + EPS);
        g_s3[d] = s3;
        g_t3[d] = (b_eu[d] - m3[d]) * s3 + b3[d];
    }
    if (d < CCH) {
        float s5 = g5[d] * rsqrtf(v5[d] + EPS);
        g_s5[d] = s5;
        g_t5[d] = b5[d] - m5[d] * s5;
    }
    if (d == 0) {
        float s1 = g1[0] * rsqrtf(v1[0] + EPS);
        #pragma unroll
        for (int n = 0; n < 4; n++) g_wa[n] = w_ea[n] * s1;
        g_ca = (b_ea[0] - m1[0]) * s1 + b1[0];
        float s4 = g4[0] * rsqrtf(v4[0] + EPS);
        #pragma unroll
        for (int n = 0; n < 4; n++) g_wr[n] = w_er[n] * s4;
        g_cr = (b_er[0] - m4[0]) * s4 + b4[0];
    }
}

// ---------------- weight prep: transpose [K][N] -> [N][K], split hi/lo ----------
// W=0: w_vu (K=1024,N=256) -> vuT ; W=1: w_eu[0:512] -> wvT ;
// W=2: w_eu[512:1024] -> weT ; W=3: w_fc (K=768,N=512) -> fcT
template<int W>
__global__ void prepw(const float* __restrict__ src) {
    constexpr int K = (W == 0) ? 1024 : ((W == 3) ? 768 : 512);
    constexpr int N = (W == 3) ? 512 : 256;
    int gid = blockIdx.x * 256 + threadIdx.x;
    if (gid >= K * N) return;
    int k = gid / N, n = gid % N;
    float v = src[gid];
    __nv_bfloat16 h = __float2bfloat16(v);
    __nv_bfloat16 l = __float2bfloat16(v - __bfloat162float(h));
    size_t o = (size_t)n * K + k;
    if (W == 0) { g_vuT_hi[o] = h; g_vuT_lo[o] = l; }
    if (W == 1) { g_wvT_hi[o] = h; g_wvT_lo[o] = l; }
    if (W == 2) { g_weT_hi[o] = h; g_weT_lo[o] = l; }
    if (W == 3) { g_fcT_hi[o] = h; g_fcT_lo[o] = l; }
}

// ---------------- elementwise: agg + neighbor products + splits ----------------
__global__ void aggsplit_k(const float* __restrict__ X) {
    int idx = blockIdx.x * 256 + threadIdx.x;   // over 8192*128 float4s
    int p = idx >> 7;
    int c = (idx & 127) << 2;
    int h = (p >> 6) & 63, w = p & 63;
    int baseH = p & ~4032;
    int pu = baseH | (((h + 63) & 63) << 6);
    int pd = baseH | (((h + 1) & 63) << 6);
    int baseW = p & ~63;
    int pl = baseW | ((w + 63) & 63);
    int pr = baseW | ((w + 1) & 63);
    float4 xv = *(const float4*)(X + (size_t)p  * 512 + c);
    float4 xu = *(const float4*)(X + (size_t)pu * 512 + c);
    float4 xd = *(const float4*)(X + (size_t)pd * 512 + c);
    float4 xl = *(const float4*)(X + (size_t)pl * 512 + c);
    float4 xr = *(const float4*)(X + (size_t)pr * 512 + c);
    float w0 = g_wa[0], w1 = g_wa[1], w2 = g_wa[2], w3 = g_wa[3], ca = g_ca;
    float4 ag, pv, ph;
    ag.x = fmaxf(fmaf(xv.x, w0 * xu.x + w1 * xd.x + w2 * xl.x + w3 * xr.x, ca), 0.f);
    ag.y = fmaxf(fmaf(xv.y, w0 * xu.y + w1 * xd.y + w2 * xl.y + w3 * xr.y, ca), 0.f);
    ag.z = fmaxf(fmaf(xv.z, w0 * xu.z + w1 * xd.z + w2 * xl.z + w3 * xr.z, ca), 0.f);
    ag.w = fmaxf(fmaf(xv.w, w0 * xu.w + w1 * xd.w + w2 * xl.w + w3 * xr.w, ca), 0.f);
    pv = make_float4(xv.x * xu.x, xv.y * xu.y, xv.z * xu.z, xv.w * xu.w);
    ph = make_float4(xv.x * xl.x, xv.y * xl.y, xv.z * xl.z, xv.w * xl.w);

    size_t o = (size_t)p * 512 + c;
    uint2 hh, ll;
    sp4(xv, hh, ll);
    *(uint2*)(g_xs_hi + o) = hh; *(uint2*)(g_xs_lo + o) = ll;
    sp4(pv, hh, ll);
    *(uint2*)(g_pv_hi + o) = hh; *(uint2*)(g_pv_lo + o) = ll;
    sp4(ph, hh, ll);
    *(uint2*)(g_ph_hi + o) = hh; *(uint2*)(g_ph_lo + o) = ll;
    sp4(ag, hh, ll);
    *(uint2*)(g_ag_hi + o) = hh; *(uint2*)(g_ag_lo + o) = ll;
}

// ---------------- edge reduce + vertex*edge product (-> split upd) ----------------
__global__ void ur_k() {
    int idx = blockIdx.x * 256 + threadIdx.x;   // over 8192*64 float4s
    int p = idx >> 6;
    int d = (idx & 63) << 2;
    int h = (p >> 6) & 63, w = p & 63;
    int pdn = (p & ~4032) | (((h + 1) & 63) << 6);
    int prt = (p & ~63)   | ((w + 1) & 63);
    const float4 A  = *(const float4*)(g_A  + (size_t)p   * 256 + d);
    const float4 e0 = *(const float4*)(g_Pv + (size_t)p   * 256 + d);
    const float4 e1 = *(const float4*)(g_Pv + (size_t)pdn * 256 + d);
    const float4 e2 = *(const float4*)(g_Ph + (size_t)p   * 256 + d);
    const float4 e3 = *(const float4*)(g_Ph + (size_t)prt * 256 + d);
    const float4 s3 = *(const float4*)(g_s3 + d);
    const float4 t3 = *(const float4*)(g_t3 + d);
    const float4 uv = *(const float4*)(g_uv + (size_t)p * 256 + d);
    float w0 = g_wr[0], w1 = g_wr[1], w2 = g_wr[2], w3 = g_wr[3], cr = g_cr;
    float4 o;
#define UR_COMP(f)                                                      \
    {                                                                   \
        float u0 = fmaxf(fmaf(A.f + e0.f, s3.f, t3.f), 0.f);            \
        float u1 = fmaxf(fmaf(A.f + e1.f, s3.f, t3.f), 0.f);            \
        float u2 = fmaxf(fmaf(A.f + e2.f, s3.f, t3.f), 0.f);            \
        float u3 = fmaxf(fmaf(A.f + e3.f, s3.f, t3.f), 0.f);            \
        float rr = fmaxf(w0*u0 + w1*u1 + w2*u2 + w3*u3 + cr, 0.f);      \
        o.f = uv.f * rr;                                                \
    }
    UR_COMP(x) UR_COMP(y) UR_COMP(z) UR_COMP(w)
#undef UR_COMP
    uint2 hh, ll;
    sp4(o, hh, ll);
    size_t off = (size_t)p * 256 + d;
    *(uint2*)(g_up_hi + off) = hh;
    *(uint2*)(g_up_lo + off) = ll;
}

// ---------------- HMMA GEMM (mma.sync bf16 split, 128x128x32, 256 thr) ----------
// PHASE 0, z: 0: A=xs@wvT -> g_A ; 1: pvs@weT -> g_Pv ; 2: phs@weT -> g_Ph ;
//             3: [xs|aggs]@vuT -> g_uv (relu s2,t2)
// PHASE 1:    [xs|upds]@fcT -> d_out (relu s5,t5), n0 = blockIdx.y*128
static constexpr int STAGE   = 32768;            // 4 x 8KB (Ahi,Alo,Bhi,Blo)
static constexpr int OFF_AH  = 0;
static constexpr int OFF_AL  = 8192;
static constexpr int OFF_BH  = 16384;
static constexpr int OFF_BL  = 24576;
static constexpr int SMEM_SZ = 3 * STAGE;        // 98304

template<int PHASE>
__global__ __launch_bounds__(256, 1) void mma_gemm(float* __restrict__ OutFc) {
    extern __shared__ char sm[];
    const uint32_t sb = s2u(sm);
    const int tid = threadIdx.x, wid = tid >> 5, lane = tid & 31;
    const int m0 = blockIdx.x * 128, n0 = blockIdx.y * 128;
    const int z = (PHASE == 0) ? (int)blockIdx.z : 4;

    int KT;
    const __nv_bfloat16 *Bhi_, *Blo_;
    if (PHASE == 0) {
        if (z == 0)      { KT = 512;  Bhi_ = g_wvT_hi; Blo_ = g_wvT_lo; }
        else if (z == 1) { KT = 512;  Bhi_ = g_weT_hi; Blo_ = g_weT_lo; }
        else if (z == 2) { KT = 512;  Bhi_ = g_weT_hi; Blo_ = g_weT_lo; }
        else             { KT = 1024; Bhi_ = g_vuT_hi; Blo_ = g_vuT_lo; }
    } else { KT = 768; Bhi_ = g_fcT_hi; Blo_ = g_fcT_lo; }
    const int NIT = KT / 32;

    // per-thread cp.async coords: row = tid>>1 (0..127), chunks cc, cc+1
    const int lrow = tid >> 1;
    const int cc = (tid & 1) * 2;
    const uint32_t so0 = (uint32_t)(lrow * 64 + ((cc ^ ((lrow >> 1) & 3)) << 4));
    const uint32_t so1 = so0 ^ 16;

    auto load_stage = [&](int it) {
        const int k0 = it * 32;
        const uint32_t s = sb + (uint32_t)(it % 3) * STAGE;
        // pick A segment
        const __nv_bfloat16 *ahi, *alo;
        int astr, ak;
        if (PHASE == 0) {
            if (z == 0)      { ahi = g_xs_hi; alo = g_xs_lo; astr = 512; ak = k0; }
            else if (z == 1) { ahi = g_pv_hi; alo = g_pv_lo; astr = 512; ak = k0; }
            else if (z == 2) { ahi = g_ph_hi; alo = g_ph_lo; astr = 512; ak = k0; }
            else {
                if (k0 < 512) { ahi = g_xs_hi; alo = g_xs_lo; astr = 512; ak = k0; }
                else          { ahi = g_ag_hi; alo = g_ag_lo; astr = 512; ak = k0 - 512; }
            }
        } else {
            if (k0 < 512) { ahi = g_xs_hi; alo = g_xs_lo; astr = 512; ak = k0; }
            else          { ahi = g_up_hi; alo = g_up_lo; astr = 256; ak = k0 - 512; }
        }
        const __nv_bfloat16* ga = ahi + (size_t)(m0 + lrow) * astr + ak + cc * 8;
        cpasync16(s + OFF_AH + so0, ga);
        cpasync16(s + OFF_AH + so1, ga + 8);
        ga = alo + (size_t)(m0 + lrow) * astr + ak + cc * 8;
        cpasync16(s + OFF_AL + so0, ga);
        cpasync16(s + OFF_AL + so1, ga + 8);
        const __nv_bfloat16* gb = Bhi_ + (size_t)(n0 + lrow) * KT + k0 + cc * 8;
        cpasync16(s + OFF_BH + so0, gb);
        cpasync16(s + OFF_BH + so1, gb + 8);
        gb = Blo_ + (size_t)(n0 + lrow) * KT + k0 + cc * 8;
        cpasync16(s + OFF_BL + so0, gb);
        cpasync16(s + OFF_BL + so1, gb + 8);
        CP_COMMIT();
    };

    const int wm = wid >> 2, wn = wid & 3;
    float acc[4][4][4];
    #pragma unroll
    for (int i = 0; i < 4; i++)
        #pragma unroll
        for (int j = 0; j < 4; j++)
            #pragma unroll
            for (int q = 0; q < 4; q++) acc[i][j][q] = 0.f;

    // frag ldsm coords
    const int arow_l = lane & 15;
    const int abump  = lane >> 4;                       // 0/1 -> chunk +0/+1
    const int brow_l = (lane & 7) + ((lane >> 4) << 3); // rows 0-7 / 8-15
    const int bbump  = (lane >> 3) & 1;

    auto compute = [&](int it) {
        const uint32_t s = sb + (uint32_t)(it % 3) * STAGE;
        #pragma unroll
        for (int ks = 0; ks < 2; ks++) {
            const int cb = ks * 2;
            uint32_t ah[4][4], al[4][4], bh[2][4], bl[2][4];
            #pragma unroll
            for (int mt = 0; mt < 4; mt++) {
                int rr = wm * 64 + mt * 16 + arow_l;
                int ch = cb + abump;
                uint32_t ad = s + OFF_AH + rr * 64 + ((ch ^ ((rr >> 1) & 3)) << 4);
                ldsm4(ah[mt], ad);
                ldsm4(al[mt], ad + (OFF_AL - OFF_AH));
            }
            #pragma unroll
            for (int np = 0; np < 2; np++) {
                int rr = wn * 32 + np * 16 + brow_l;
                int ch = cb + bbump;
                uint32_t bd = s + OFF_BH + rr * 64 + ((ch ^ ((rr >> 1) & 3)) << 4);
                ldsm4(bh[np], bd);
                ldsm4(bl[np], bd + (OFF_BL - OFF_BH));
            }
            #pragma unroll
            for (int mt = 0; mt < 4; mt++)
                #pragma unroll
                for (int nt = 0; nt < 4; nt++) {
                    const uint32_t* bhp = &bh[nt >> 1][(nt & 1) * 2];
                    const uint32_t* blp = &bl[nt >> 1][(nt & 1) * 2];
                    mma16816(acc[mt][nt], ah[mt], bhp);
                    mma16816(acc[mt][nt], ah[mt], blp);
                    mma16816(acc[mt][nt], al[mt], bhp);
                }
        }
    };

    load_stage(0);
    load_stage(1);
    for (int it = 0; it < NIT; it++) {
        if (it < NIT - 1) { CP_WAIT(1); } else { CP_WAIT(0); }
        __syncthreads();
        compute(it);
        if (it + 2 < NIT) load_stage(it + 2);
    }

    // ---- epilogue ----
    #pragma unroll
    for (int mt = 0; mt < 4; mt++) {
        const int row = m0 + wm * 64 + mt * 16 + (lane >> 2);
        #pragma unroll
        for (int nt = 0; nt < 4; nt++) {
            const int lc = wn * 32 + nt * 8 + (lane & 3) * 2;
            const int gc = n0 + lc;
            float* d = acc[mt][nt];
            if (PHASE == 0 && z < 3) {
                float* Out = (z == 0) ? g_A : (z == 1) ? g_Pv : g_Ph;
                *(float2*)(Out + (size_t)row * 256 + gc)       = make_float2(d[0], d[1]);
                *(float2*)(Out + (size_t)(row + 8) * 256 + gc) = make_float2(d[2], d[3]);
            } else if (PHASE == 0) {
                float s0 = g_s2[gc], s1 = g_s2[gc + 1];
                float t0 = g_t2[gc], t1 = g_t2[gc + 1];
                *(float2*)(g_uv + (size_t)row * 256 + gc) =
                    make_float2(fmaxf(fmaf(d[0], s0, t0), 0.f), fmaxf(fmaf(d[1], s1, t1), 0.f));
                *(float2*)(g_uv + (size_t)(row + 8) * 256 + gc) =
                    make_float2(fmaxf(fmaf(d[2], s0, t0), 0.f), fmaxf(fmaf(d[3], s1, t1), 0.f));
            } else {
                float s0 = g_s5[gc], s1 = g_s5[gc + 1];
                float t0 = g_t5[gc], t1 = g_t5[gc + 1];
                *(float2*)(OutFc + (size_t)row * 512 + gc) =
                    make_float2(fmaxf(fmaf(d[0], s0, t0), 0.f), fmaxf(fmaf(d[1], s1, t1), 0.f));
                *(float2*)(OutFc + (size_t)(row + 8) * 512 + gc) =
                    make_float2(fmaxf(fmaf(d[2], s0, t0), 0.f), fmaxf(fmaf(d[3], s1, t1), 0.f));
            }
        }
    }
}

// ---------------- launch ----------------
extern "C" void kernel_launch(void* const* d_in, const int* in_sizes, int n_in,
                              void* d_out, int out_size) {
    const float* x    = (const float*)d_in[0];
    const float* w_ea = (const float*)d_in[1];
    const float* b_ea = (const float*)d_in[2];
    const float* g1   = (const float*)d_in[3];
    const float* b1   = (const float*)d_in[4];
    const float* m1   = (const float*)d_in[5];
    const float* v1   = (const float*)d_in[6];
    const float* w_vu = (const float*)d_in[7];
    const float* b_vu = (const float*)d_in[8];
    const float* g2   = (const float*)d_in[9];
    const float* b2   = (const float*)d_in[10];
    const float* m2   = (const float*)d_in[11];
    const float* v2   = (const float*)d_in[12];
    const float* w_eu = (const float*)d_in[13];
    const float* b_eu = (const float*)d_in[14];
    const float* g3   = (const float*)d_in[15];
    const float* b3   = (const float*)d_in[16];
    const float* m3   = (const float*)d_in[17];
    const float* v3   = (const float*)d_in[18];
    const float* w_er = (const float*)d_in[19];
    const float* b_er = (const float*)d_in[20];
    const float* g4   = (const float*)d_in[21];
    const float* b4   = (const float*)d_in[22];
    const float* m4   = (const float*)d_in[23];
    const float* v4   = (const float*)d_in[24];
    const float* w_fc = (const float*)d_in[25];
    const float* g5   = (const float*)d_in[26];
    const float* b5   = (const float*)d_in[27];
    const float* m5   = (const float*)d_in[28];
    const float* v5   = (const float*)d_in[29];

    cudaFuncSetAttribute((const void*)mma_gemm<0>,
                         cudaFuncAttributeMaxDynamicSharedMemorySize, SMEM_SZ);
    cudaFuncSetAttribute((const void*)mma_gemm<1>,
                         cudaFuncAttributeMaxDynamicSharedMemorySize, SMEM_SZ);

    fold_k<<<1, 512>>>(w_ea, b_ea, g1, b1, m1, v1,
                       b_vu, g2, b2, m2, v2,
                       b_eu, g3, b3, m3, v3,
                       w_er, b_er, g4, b4, m4, v4,
                       g5, b5, m5, v5);
    prepw<0><<<1024, 256>>>(w_vu);
    prepw<1><<<512, 256>>>(w_eu);
    prepw<2><<<512, 256>>>(w_eu + 512 * 256);
    prepw<3><<<1536, 256>>>(w_fc);

    aggsplit_k<<<4096, 256>>>(x);                               // splits + agg + products
    mma_gemm<0><<<dim3(64, 2, 4), 256, SMEM_SZ>>>(nullptr);     // g_A,g_Pv,g_Ph,g_uv
    ur_k<<<2048, 256>>>();                                      // -> g_up (split)
    mma_gemm<1><<<dim3(64, 4, 1), 256, SMEM_SZ>>>((float*)d_out);
}

// round 8
// speedup vs baseline: 6.0719x; 1.9424x over previous
#include <cuda_runtime.h>
#include <cuda_fp16.h>
#include <cstdint>

#define EPS 1e-3f

static constexpr int MROWS = 8192;   // B*H*W
static constexpr int CCH   = 512;
static constexpr int CH2   = 256;

// ---------------- scratch (device globals; no allocs allowed) ----------------
// fp32 intermediates for the elementwise combine
__device__ __align__(16) float g_A  [MROWS * CH2];
__device__ __align__(16) float g_Pv [MROWS * CH2];
__device__ __align__(16) float g_Ph [MROWS * CH2];
__device__ __align__(16) float g_uv [MROWS * CH2];

// fp16 activation operands
__device__ __align__(16) __half g_xs[MROWS * CCH];
__device__ __align__(16) __half g_pv[MROWS * CCH];
__device__ __align__(16) __half g_ph[MROWS * CCH];
__device__ __align__(16) __half g_ag[MROWS * CCH];
__device__ __align__(16) __half g_up[MROWS * CH2];

// fp16 weights, transposed to [N][K] (k contiguous)
__device__ __align__(16) __half g_vuT[256 * 1024];
__device__ __align__(16) __half g_wvT[256 *  512];
__device__ __align__(16) __half g_weT[256 *  512];
__device__ __align__(16) __half g_fcT[512 *  768];

__device__ __align__(16) float g_s2[CH2], g_t2[CH2], g_s3[CH2], g_t3[CH2];
__device__ __align__(16) float g_s5[CCH], g_t5[CCH];
__device__ float g_wa[4], g_wr[4], g_ca, g_cr;

// ---------------- PTX helpers ----------------
__device__ __forceinline__ uint32_t s2u(const void* p) {
    uint32_t a;
    asm("{ .reg .u64 t; cvta.to.shared.u64 t, %1; cvt.u32.u64 %0, t; }" : "=r"(a) : "l"(p));
    return a;
}
__device__ __forceinline__ void cpasync16(uint32_t s, const void* g) {
    asm volatile("cp.async.cg.shared.global [%0], [%1], 16;" :: "r"(s), "l"(g));
}
#define CP_COMMIT() asm volatile("cp.async.commit_group;" ::: "memory")
#define CP_WAIT(n)  asm volatile("cp.async.wait_group %0;" :: "n"(n) : "memory")

__device__ __forceinline__ void ldsm4(uint32_t* r, uint32_t addr) {
    asm volatile("ldmatrix.sync.aligned.m8n8.x4.shared.b16 {%0,%1,%2,%3}, [%4];"
                 : "=r"(r[0]), "=r"(r[1]), "=r"(r[2]), "=r"(r[3]) : "r"(addr));
}
__device__ __forceinline__ void mma16816(float* d, const uint32_t* a, const uint32_t* b) {
    asm volatile(
        "mma.sync.aligned.m16n8k16.row.col.f32.f16.f16.f32 "
        "{%0,%1,%2,%3}, {%4,%5,%6,%7}, {%8,%9}, {%0,%1,%2,%3};"
        : "+f"(d[0]), "+f"(d[1]), "+f"(d[2]), "+f"(d[3])
        : "r"(a[0]), "r"(a[1]), "r"(a[2]), "r"(a[3]), "r"(b[0]), "r"(b[1]));
}

// pack float4 -> 4x fp16 (uint2) — bit-cast intrinsics only, no address-of locals
__device__ __forceinline__ uint2 pk4(float4 v) {
    uint2 r;
    r.x = (uint32_t)__half_as_ushort(__float2half_rn(v.x)) |
          ((uint32_t)__half_as_ushort(__float2half_rn(v.y)) << 16);
    r.y = (uint32_t)__half_as_ushort(__float2half_rn(v.z)) |
          ((uint32_t)__half_as_ushort(__float2half_rn(v.w)) << 16);
    return r;
}

// ---------------- param folding ----------------
__global__ void fold_k(const float* w_ea, const float* b_ea,
                       const float* g1, const float* b1, const float* m1, const float* v1,
                       const float* b_vu,
                       const float* g2, const float* b2, const float* m2, const float* v2,
                       const float* b_eu,
                       const float* g3, const float* b3, const float* m3, const float* v3,
                       const float* w_er, const float* b_er,
                       const float* g4, const float* b4, const float* m4, const float* v4,
                       const float* g5, const float* b5, const float* m5, const float* v5) {
    int d = threadIdx.x;
    if (d < CH2) {
        float s2 = g2[d] * rsqrtf(v2[d] + EPS);
        g_s2[d] = s2;
        g_t2[d] = (b_vu[d] - m2[d]) * s2 + b2[d];
        float s3 = g3[d] * rsqrtf(v3[d] + EPS);
        g_s3[d] = s3;
        g_t3[d] = (b_eu[d] - m3[d]) * s3 + b3[d];
    }
    if (d < CCH) {
        float s5 = g5[d] * rsqrtf(v5[d] + EPS);
        g_s5[d] = s5;
        g_t5[d] = b5[d] - m5[d] * s5;
    }
    if (d == 0) {
        float s1 = g1[0] * rsqrtf(v1[0] + EPS);
        #pragma unroll
        for (int n = 0; n < 4; n++) g_wa[n] = w_ea[n] * s1;
        g_ca = (b_ea[0] - m1[0]) * s1 + b1[0];
        float s4 = g4[0] * rsqrtf(v4[0] + EPS);
        #pragma unroll
        for (int n = 0; n < 4; n++) g_wr[n] = w_er[n] * s4;
        g_cr = (b_er[0] - m4[0]) * s4 + b4[0];
    }
}

// ---------------- weight prep: tiled transpose [K][N] -> [N][K] + fp16 ----------
// Destination global is selected IN DEVICE CODE (passing a __device__ array as a
// host-side kernel argument is invalid — the host sees only the shadow symbol).
// W=0: w_vu -> g_vuT ; W=1: w_eu[0:512] -> g_wvT ; W=2: w_eu[512:] -> g_weT ;
// W=3: w_fc -> g_fcT
template<int W>
__global__ void prepw_t(const float* __restrict__ src) {
    constexpr int K = (W == 0) ? 1024 : ((W == 3) ? 768 : 512);
    constexpr int N = (W == 3) ? 512 : 256;
    __half* dst = (W == 0) ? g_vuT : (W == 1) ? g_wvT : (W == 2) ? g_weT : g_fcT;
    __shared__ float t[32][33];
    const int k0 = blockIdx.x * 32, n0 = blockIdx.y * 32;
    const int r = threadIdx.x >> 5, c = threadIdx.x & 31;   // 8 x 32
    #pragma unroll
    for (int i = 0; i < 4; i++)
        t[r + 8 * i][c] = src[(size_t)(k0 + r + 8 * i) * N + n0 + c];
    __syncthreads();
    #pragma unroll
    for (int i = 0; i < 4; i++)
        dst[(size_t)(n0 + r + 8 * i) * K + k0 + c] = __float2half_rn(t[c][r + 8 * i]);
}

// ---------------- elementwise: agg + neighbor products + fp16 stores ----------------
__global__ void aggsplit_k(const float* __restrict__ X) {
    int idx = blockIdx.x * 256 + threadIdx.x;   // over 8192*128 float4s
    int p = idx >> 7;
    int c = (idx & 127) << 2;
    int h = (p >> 6) & 63, w = p & 63;
    int baseH = p & ~4032;
    int pu = baseH | (((h + 63) & 63) << 6);
    int pd = baseH | (((h + 1) & 63) << 6);
    int baseW = p & ~63;
    int pl = baseW | ((w + 63) & 63);
    int pr = baseW | ((w + 1) & 63);
    float4 xv = *(const float4*)(X + (size_t)p  * 512 + c);
    float4 xu = *(const float4*)(X + (size_t)pu * 512 + c);
    float4 xd = *(const float4*)(X + (size_t)pd * 512 + c);
    float4 xl = *(const float4*)(X + (size_t)pl * 512 + c);
    float4 xr = *(const float4*)(X + (size_t)pr * 512 + c);
    float w0 = g_wa[0], w1 = g_wa[1], w2 = g_wa[2], w3 = g_wa[3], ca = g_ca;
    float4 ag, pv, ph;
    ag.x = fmaxf(fmaf(xv.x, w0 * xu.x + w1 * xd.x + w2 * xl.x + w3 * xr.x, ca), 0.f);
    ag.y = fmaxf(fmaf(xv.y, w0 * xu.y + w1 * xd.y + w2 * xl.y + w3 * xr.y, ca), 0.f);
    ag.z = fmaxf(fmaf(xv.z, w0 * xu.z + w1 * xd.z + w2 * xl.z + w3 * xr.z, ca), 0.f);
    ag.w = fmaxf(fmaf(xv.w, w0 * xu.w + w1 * xd.w + w2 * xl.w + w3 * xr.w, ca), 0.f);
    pv = make_float4(xv.x * xu.x, xv.y * xu.y, xv.z * xu.z, xv.w * xu.w);
    ph = make_float4(xv.x * xl.x, xv.y * xl.y, xv.z * xl.z, xv.w * xl.w);

    size_t o = (size_t)p * 512 + c;
    *(uint2*)(g_xs + o) = pk4(xv);
    *(uint2*)(g_pv + o) = pk4(pv);
    *(uint2*)(g_ph + o) = pk4(ph);
    *(uint2*)(g_ag + o) = pk4(ag);
}

// ---------------- edge reduce + vertex*edge product (-> fp16 upd) ----------------
__global__ void ur_k() {
    int idx = blockIdx.x * 256 + threadIdx.x;   // over 8192*64 float4s
    int p = idx >> 6;
    int d = (idx & 63) << 2;
    int h = (p >> 6) & 63, w = p & 63;
    int pdn = (p & ~4032) | (((h + 1) & 63) << 6);
    int prt = (p & ~63)   | ((w + 1) & 63);
    const float4 A  = *(const float4*)(g_A  + (size_t)p   * 256 + d);
    const float4 e0 = *(const float4*)(g_Pv + (size_t)p   * 256 + d);
    const float4 e1 = *(const float4*)(g_Pv + (size_t)pdn * 256 + d);
    const float4 e2 = *(const float4*)(g_Ph + (size_t)p   * 256 + d);
    const float4 e3 = *(const float4*)(g_Ph + (size_t)prt * 256 + d);
    const float4 s3 = *(const float4*)(g_s3 + d);
    const float4 t3 = *(const float4*)(g_t3 + d);
    const float4 uv = *(const float4*)(g_uv + (size_t)p * 256 + d);
    float w0 = g_wr[0], w1 = g_wr[1], w2 = g_wr[2], w3 = g_wr[3], cr = g_cr;
    float4 o;
#define UR_COMP(f)                                                      \
    {                                                                   \
        float u0 = fmaxf(fmaf(A.f + e0.f, s3.f, t3.f), 0.f);            \
        float u1 = fmaxf(fmaf(A.f + e1.f, s3.f, t3.f), 0.f);            \
        float u2 = fmaxf(fmaf(A.f + e2.f, s3.f, t3.f), 0.f);            \
        float u3 = fmaxf(fmaf(A.f + e3.f, s3.f, t3.f), 0.f);            \
        float rr = fmaxf(w0*u0 + w1*u1 + w2*u2 + w3*u3 + cr, 0.f);      \
        o.f = uv.f * rr;                                                \
    }
    UR_COMP(x) UR_COMP(y) UR_COMP(z) UR_COMP(w)
#undef UR_COMP
    *(uint2*)(g_up + (size_t)p * 256 + d) = pk4(o);
}

// ---------------- HMMA GEMM (mma.sync fp16, 128x128x32, 256 thr) ----------
// PHASE 0, z: 0: xs@wvT -> g_A ; 1: pv@weT -> g_Pv ; 2: ph@weT -> g_Ph ;
//             3: [xs|ag]@vuT -> g_uv (relu s2,t2)
// PHASE 1:    [xs|up]@fcT -> d_out (relu s5,t5), n0 = blockIdx.y*128
static constexpr int STAGE   = 16384;            // 8KB A + 8KB B
static constexpr int OFF_A   = 0;
static constexpr int OFF_B   = 8192;
static constexpr int SMEM_SZ = 3 * STAGE;        // 49152

template<int PHASE>
__global__ __launch_bounds__(256, 1) void mma_gemm(float* __restrict__ OutFc) {
    extern __shared__ char sm[];
    const uint32_t sb = s2u(sm);
    const int tid = threadIdx.x, wid = tid >> 5, lane = tid & 31;
    const int m0 = blockIdx.x * 128, n0 = blockIdx.y * 128;
    const int z = (PHASE == 0) ? (int)blockIdx.z : 4;

    int KT;
    const __half* B_;
    if (PHASE == 0) {
        if (z == 0)      { KT = 512;  B_ = g_wvT; }
        else if (z == 1) { KT = 512;  B_ = g_weT; }
        else if (z == 2) { KT = 512;  B_ = g_weT; }
        else             { KT = 1024; B_ = g_vuT; }
    } else { KT = 768; B_ = g_fcT; }
    const int NIT = KT / 32;

    // per-thread cp.async coords: row = tid>>1 (0..127), chunks cc, cc+1
    const int lrow = tid >> 1;
    const int cc = (tid & 1) * 2;
    const uint32_t so0 = (uint32_t)(lrow * 64 + ((cc ^ ((lrow >> 1) & 3)) << 4));
    const uint32_t so1 = so0 ^ 16;

    auto load_stage = [&](int it) {
        const int k0 = it * 32;
        const uint32_t s = sb + (uint32_t)(it % 3) * STAGE;
        const __half* a_;
        int astr, ak;
        if (PHASE == 0) {
            if (z == 0)      { a_ = g_xs; astr = 512; ak = k0; }
            else if (z == 1) { a_ = g_pv; astr = 512; ak = k0; }
            else if (z == 2) { a_ = g_ph; astr = 512; ak = k0; }
            else {
                if (k0 < 512) { a_ = g_xs; astr = 512; ak = k0; }
                else          { a_ = g_ag; astr = 512; ak = k0 - 512; }
            }
        } else {
            if (k0 < 512) { a_ = g_xs; astr = 512; ak = k0; }
            else          { a_ = g_up; astr = 256; ak = k0 - 512; }
        }
        const __half* ga = a_ + (size_t)(m0 + lrow) * astr + ak + cc * 8;
        cpasync16(s + OFF_A + so0, ga);
        cpasync16(s + OFF_A + so1, ga + 8);
        const __half* gb = B_ + (size_t)(n0 + lrow) * KT + k0 + cc * 8;
        cpasync16(s + OFF_B + so0, gb);
        cpasync16(s + OFF_B + so1, gb + 8);
        CP_COMMIT();
    };

    const int wm = wid >> 2, wn = wid & 3;
    float acc[4][4][4];
    #pragma unroll
    for (int i = 0; i < 4; i++)
        #pragma unroll
        for (int j = 0; j < 4; j++)
            #pragma unroll
            for (int q = 0; q < 4; q++) acc[i][j][q] = 0.f;

    // frag ldsm coords
    const int arow_l = lane & 15;
    const int abump  = lane >> 4;                       // 0/1 -> chunk +0/+1
    const int brow_l = (lane & 7) + ((lane >> 4) << 3); // rows 0-7 / 8-15
    const int bbump  = (lane >> 3) & 1;

    auto compute = [&](int it) {
        const uint32_t s = sb + (uint32_t)(it % 3) * STAGE;
        #pragma unroll
        for (int ks = 0; ks < 2; ks++) {
            const int cb = ks * 2;
            uint32_t ah[4][4], bh[2][4];
            #pragma unroll
            for (int mt = 0; mt < 4; mt++) {
                int rr = wm * 64 + mt * 16 + arow_l;
                int ch = cb + abump;
                uint32_t ad = s + OFF_A + rr * 64 + ((ch ^ ((rr >> 1) & 3)) << 4);
                ldsm4(ah[mt], ad);
            }
            #pragma unroll
            for (int np = 0; np < 2; np++) {
                int rr = wn * 32 + np * 16 + brow_l;
                int ch = cb + bbump;
                uint32_t bd = s + OFF_B + rr * 64 + ((ch ^ ((rr >> 1) & 3)) << 4);
                ldsm4(bh[np], bd);
            }
            #pragma unroll
            for (int mt = 0; mt < 4; mt++)
                #pragma unroll
                for (int nt = 0; nt < 4; nt++)
                    mma16816(acc[mt][nt], ah[mt], &bh[nt >> 1][(nt & 1) * 2]);
        }
    };

    load_stage(0);
    load_stage(1);
    for (int it = 0; it < NIT; it++) {
        if (it < NIT - 1) { CP_WAIT(1); } else { CP_WAIT(0); }
        __syncthreads();
        compute(it);
        if (it + 2 < NIT) load_stage(it + 2);
    }

    // ---- epilogue ----
    #pragma unroll
    for (int mt = 0; mt < 4; mt++) {
        const int row = m0 + wm * 64 + mt * 16 + (lane >> 2);
        #pragma unroll
        for (int nt = 0; nt < 4; nt++) {
            const int lc = wn * 32 + nt * 8 + (lane & 3) * 2;
            const int gc = n0 + lc;
            float* d = acc[mt][nt];
            if (PHASE == 0 && z < 3) {
                float* Out = (z == 0) ? g_A : (z == 1) ? g_Pv : g_Ph;
                *(float2*)(Out + (size_t)row * 256 + gc)       = make_float2(d[0], d[1]);
                *(float2*)(Out + (size_t)(row + 8) * 256 + gc) = make_float2(d[2], d[3]);
            } else if (PHASE == 0) {
                float s0 = g_s2[gc], s1 = g_s2[gc + 1];
                float t0 = g_t2[gc], t1 = g_t2[gc + 1];
                *(float2*)(g_uv + (size_t)row * 256 + gc) =
                    make_float2(fmaxf(fmaf(d[0], s0, t0), 0.f), fmaxf(fmaf(d[1], s1, t1), 0.f));
                *(float2*)(g_uv + (size_t)(row + 8) * 256 + gc) =
                    make_float2(fmaxf(fmaf(d[2], s0, t0), 0.f), fmaxf(fmaf(d[3], s1, t1), 0.f));
            } else {
                float s0 = g_s5[gc], s1 = g_s5[gc + 1];
                float t0 = g_t5[gc], t1 = g_t5[gc + 1];
                *(float2*)(OutFc + (size_t)row * 512 + gc) =
                    make_float2(fmaxf(fmaf(d[0], s0, t0), 0.f), fmaxf(fmaf(d[1], s1, t1), 0.f));
                *(float2*)(OutFc + (size_t)(row + 8) * 512 + gc) =
                    make_float2(fmaxf(fmaf(d[2], s0, t0), 0.f), fmaxf(fmaf(d[3], s1, t1), 0.f));
            }
        }
    }
}

// ---------------- launch ----------------
extern "C" void kernel_launch(void* const* d_in, const int* in_sizes, int n_in,
                              void* d_out, int out_size) {
    const float* x    = (const float*)d_in[0];
    const float* w_ea = (const float*)d_in[1];
    const float* b_ea = (const float*)d_in[2];
    const float* g1   = (const float*)d_in[3];
    const float* b1   = (const float*)d_in[4];
    const float* m1   = (const float*)d_in[5];
    const float* v1   = (const float*)d_in[6];
    const float* w_vu = (const float*)d_in[7];
    const float* b_vu = (const float*)d_in[8];
    const float* g2   = (const float*)d_in[9];
    const float* b2   = (const float*)d_in[10];
    const float* m2   = (const float*)d_in[11];
    const float* v2   = (const float*)d_in[12];
    const float* w_eu = (const float*)d_in[13];
    const float* b_eu = (const float*)d_in[14];
    const float* g3   = (const float*)d_in[15];
    const float* b3   = (const float*)d_in[16];
    const float* m3   = (const float*)d_in[17];
    const float* v3   = (const float*)d_in[18];
    const float* w_er = (const float*)d_in[19];
    const float* b_er = (const float*)d_in[20];
    const float* g4   = (const float*)d_in[21];
    const float* b4   = (const float*)d_in[22];
    const float* m4   = (const float*)d_in[23];
    const float* v4   = (const float*)d_in[24];
    const float* w_fc = (const float*)d_in[25];
    const float* g5   = (const float*)d_in[26];
    const float* b5   = (const float*)d_in[27];
    const float* m5   = (const float*)d_in[28];
    const float* v5   = (const float*)d_in[29];

    cudaFuncSetAttribute((const void*)mma_gemm<0>,
                         cudaFuncAttributeMaxDynamicSharedMemorySize, SMEM_SZ);
    cudaFuncSetAttribute((const void*)mma_gemm<1>,
                         cudaFuncAttributeMaxDynamicSharedMemorySize, SMEM_SZ);

    fold_k<<<1, 512>>>(w_ea, b_ea, g1, b1, m1, v1,
                       b_vu, g2, b2, m2, v2,
                       b_eu, g3, b3, m3, v3,
                       w_er, b_er, g4, b4, m4, v4,
                       g5, b5, m5, v5);
    prepw_t<0><<<dim3(32, 8),  256>>>(w_vu);
    prepw_t<1><<<dim3(16, 8),  256>>>(w_eu);
    prepw_t<2><<<dim3(16, 8),  256>>>(w_eu + 512 * 256);
    prepw_t<3><<<dim3(24, 16), 256>>>(w_fc);

    aggsplit_k<<<4096, 256>>>(x);                               // fp16 xs/pv/ph/ag
    mma_gemm<0><<<dim3(64, 2, 4), 256, SMEM_SZ>>>(nullptr);     // g_A,g_Pv,g_Ph,g_uv
    ur_k<<<2048, 256>>>();                                      // -> g_up (fp16)
    mma_gemm<1><<<dim3(64, 4, 1), 256, SMEM_SZ>>>((float*)d_out);
}

// round 9
// speedup vs baseline: 6.2644x; 1.0317x over previous
#include <cuda_runtime.h>
#include <cuda_fp16.h>
#include <cstdint>

#define EPS 1e-3f

static constexpr int MROWS = 8192;   // B*H*W
static constexpr int CCH   = 512;
static constexpr int CH2   = 256;

// ---------------- scratch (device globals; no allocs allowed) ----------------
__device__ __align__(16) float g_A  [MROWS * CH2];
__device__ __align__(16) float g_Pv [MROWS * CH2];
__device__ __align__(16) float g_Ph [MROWS * CH2];
__device__ __align__(16) float g_uv [MROWS * CH2];

__device__ __align__(16) __half g_xs[MROWS * CCH];
__device__ __align__(16) __half g_pv[MROWS * CCH];
__device__ __align__(16) __half g_ph[MROWS * CCH];
__device__ __align__(16) __half g_ag[MROWS * CCH];
__device__ __align__(16) __half g_up[MROWS * CH2];

__device__ __align__(16) __half g_vuT[256 * 1024];
__device__ __align__(16) __half g_wvT[256 *  512];
__device__ __align__(16) __half g_weT[256 *  512];
__device__ __align__(16) __half g_fcT[512 *  768];

__device__ __align__(16) float g_s2[CH2], g_t2[CH2], g_s3[CH2], g_t3[CH2];
__device__ __align__(16) float g_s5[CCH], g_t5[CCH];
__device__ float g_wr[4], g_cr;

// ---------------- PTX helpers ----------------
__device__ __forceinline__ uint32_t s2u(const void* p) {
    uint32_t a;
    asm("{ .reg .u64 t; cvta.to.shared.u64 t, %1; cvt.u32.u64 %0, t; }" : "=r"(a) : "l"(p));
    return a;
}
__device__ __forceinline__ void cpasync16(uint32_t s, const void* g) {
    asm volatile("cp.async.cg.shared.global [%0], [%1], 16;" :: "r"(s), "l"(g));
}
#define CP_COMMIT() asm volatile("cp.async.commit_group;" ::: "memory")
#define CP_WAIT(n)  asm volatile("cp.async.wait_group %0;" :: "n"(n) : "memory")

__device__ __forceinline__ void ldsm4(uint32_t* r, uint32_t addr) {
    asm volatile("ldmatrix.sync.aligned.m8n8.x4.shared.b16 {%0,%1,%2,%3}, [%4];"
                 : "=r"(r[0]), "=r"(r[1]), "=r"(r[2]), "=r"(r[3]) : "r"(addr));
}
__device__ __forceinline__ void mma16816(float* d, const uint32_t* a, const uint32_t* b) {
    asm volatile(
        "mma.sync.aligned.m16n8k16.row.col.f32.f16.f16.f32 "
        "{%0,%1,%2,%3}, {%4,%5,%6,%7}, {%8,%9}, {%0,%1,%2,%3};"
        : "+f"(d[0]), "+f"(d[1]), "+f"(d[2]), "+f"(d[3])
        : "r"(a[0]), "r"(a[1]), "r"(a[2]), "r"(a[3]), "r"(b[0]), "r"(b[1]));
}

// pack float4 -> 4x fp16 (uint2) — bit-cast intrinsics only, no address-of locals
__device__ __forceinline__ uint2 pk4(float4 v) {
    uint2 r;
    r.x = (uint32_t)__half_as_ushort(__float2half_rn(v.x)) |
          ((uint32_t)__half_as_ushort(__float2half_rn(v.y)) << 16);
    r.y = (uint32_t)__half_as_ushort(__float2half_rn(v.z)) |
          ((uint32_t)__half_as_ushort(__float2half_rn(v.w)) << 16);
    return r;
}

// ---------------- fused prologue: aggsplit + 4x weight transpose + fold ---------
// block ranges:
//   [0, 4096)            : aggsplit (folded scalars re-derived locally)
//   [4096, 4352)         : prepw W0 (w_vu  -> g_vuT, 32x8 tiles)
//   [4352, 4480)         : prepw W1 (w_eu[0:512]   -> g_wvT, 16x8)
//   [4480, 4608)         : prepw W2 (w_eu[512:1024]-> g_weT, 16x8)
//   [4608, 4992)         : prepw W3 (w_fc -> g_fcT, 24x16)
//   [4992]               : fold (s2/t2/s3/t3/s5/t5, wr/cr)
template<int W>
__device__ __forceinline__ void prepw_body(const float* __restrict__ src,
                                           float (*t)[33], int bi, int tid) {
    constexpr int K = (W == 0) ? 1024 : ((W == 3) ? 768 : 512);
    constexpr int N = (W == 3) ? 512 : 256;
    constexpr int KB = K / 32;
    __half* dst = (W == 0) ? g_vuT : (W == 1) ? g_wvT : (W == 2) ? g_weT : g_fcT;
    const int k0 = (bi % KB) * 32, n0 = (bi / KB) * 32;
    const int r = tid >> 5, c = tid & 31;   // 8 x 32
    #pragma unroll
    for (int i = 0; i < 4; i++)
        t[r + 8 * i][c] = src[(size_t)(k0 + r + 8 * i) * N + n0 + c];
    __syncthreads();
    #pragma unroll
    for (int i = 0; i < 4; i++)
        dst[(size_t)(n0 + r + 8 * i) * K + k0 + c] = __float2half_rn(t[c][r + 8 * i]);
}

__global__ __launch_bounds__(256) void prep_all(
    const float* __restrict__ X,
    const float* w_ea, const float* b_ea,
    const float* g1, const float* b1, const float* m1, const float* v1,
    const float* w_vu, const float* b_vu,
    const float* g2, const float* b2, const float* m2, const float* v2,
    const float* w_eu, const float* b_eu,
    const float* g3, const float* b3, const float* m3, const float* v3,
    const float* w_er, const float* b_er,
    const float* g4, const float* b4, const float* m4, const float* v4,
    const float* w_fc,
    const float* g5, const float* b5, const float* m5, const float* v5) {
    __shared__ float t[32][33];
    const int b = blockIdx.x, tid = threadIdx.x;

    if (b < 4096) {
        // ---- aggsplit: agg + neighbor products + fp16 stores ----
        float s1 = g1[0] * rsqrtf(v1[0] + EPS);
        float w0 = w_ea[0] * s1, w1 = w_ea[1] * s1, w2 = w_ea[2] * s1, w3 = w_ea[3] * s1;
        float ca = (b_ea[0] - m1[0]) * s1 + b1[0];

        int idx = b * 256 + tid;
        int p = idx >> 7;
        int c = (idx & 127) << 2;
        int h = (p >> 6) & 63, w = p & 63;
        int baseH = p & ~4032;
        int pu = baseH | (((h + 63) & 63) << 6);
        int pd = baseH | (((h + 1) & 63) << 6);
        int baseW = p & ~63;
        int pl = baseW | ((w + 63) & 63);
        int pr = baseW | ((w + 1) & 63);
        float4 xv = *(const float4*)(X + (size_t)p  * 512 + c);
        float4 xu = *(const float4*)(X + (size_t)pu * 512 + c);
        float4 xd = *(const float4*)(X + (size_t)pd * 512 + c);
        float4 xl = *(const float4*)(X + (size_t)pl * 512 + c);
        float4 xr = *(const float4*)(X + (size_t)pr * 512 + c);
        float4 ag, pv, ph;
        ag.x = fmaxf(fmaf(xv.x, w0 * xu.x + w1 * xd.x + w2 * xl.x + w3 * xr.x, ca), 0.f);
        ag.y = fmaxf(fmaf(xv.y, w0 * xu.y + w1 * xd.y + w2 * xl.y + w3 * xr.y, ca), 0.f);
        ag.z = fmaxf(fmaf(xv.z, w0 * xu.z + w1 * xd.z + w2 * xl.z + w3 * xr.z, ca), 0.f);
        ag.w = fmaxf(fmaf(xv.w, w0 * xu.w + w1 * xd.w + w2 * xl.w + w3 * xr.w, ca), 0.f);
        pv = make_float4(xv.x * xu.x, xv.y * xu.y, xv.z * xu.z, xv.w * xu.w);
        ph = make_float4(xv.x * xl.x, xv.y * xl.y, xv.z * xl.z, xv.w * xl.w);

        size_t o = (size_t)p * 512 + c;
        *(uint2*)(g_xs + o) = pk4(xv);
        *(uint2*)(g_pv + o) = pk4(pv);
        *(uint2*)(g_ph + o) = pk4(ph);
        *(uint2*)(g_ag + o) = pk4(ag);
    } else if (b < 4352) {
        prepw_body<0>(w_vu, t, b - 4096, tid);
    } else if (b < 4480) {
        prepw_body<1>(w_eu, t, b - 4352, tid);
    } else if (b < 4608) {
        prepw_body<2>(w_eu + 512 * 256, t, b - 4480, tid);
    } else if (b < 4992) {
        prepw_body<3>(w_fc, t, b - 4608, tid);
    } else {
        // ---- fold ----
        int d = tid;
        if (d < CH2) {
            float s2 = g2[d] * rsqrtf(v2[d] + EPS);
            g_s2[d] = s2;
            g_t2[d] = (b_vu[d] - m2[d]) * s2 + b2[d];
            float s3 = g3[d] * rsqrtf(v3[d] + EPS);
            g_s3[d] = s3;
            g_t3[d] = (b_eu[d] - m3[d]) * s3 + b3[d];
        }
        #pragma unroll
        for (int dd = d; dd < CCH; dd += 256) {
            float s5 = g5[dd] * rsqrtf(v5[dd] + EPS);
            g_s5[dd] = s5;
            g_t5[dd] = b5[dd] - m5[dd] * s5;
        }
        if (d == 0) {
            float s4 = g4[0] * rsqrtf(v4[0] + EPS);
            #pragma unroll
            for (int n = 0; n < 4; n++) g_wr[n] = w_er[n] * s4;
            g_cr = (b_er[0] - m4[0]) * s4 + b4[0];
        }
    }
}

// ---------------- edge reduce + vertex*edge product (-> fp16 upd) ----------------
__global__ void ur_k() {
    int idx = blockIdx.x * 256 + threadIdx.x;   // over 8192*64 float4s
    int p = idx >> 6;
    int d = (idx & 63) << 2;
    int h = (p >> 6) & 63, w = p & 63;
    int pdn = (p & ~4032) | (((h + 1) & 63) << 6);
    int prt = (p & ~63)   | ((w + 1) & 63);
    const float4 A  = *(const float4*)(g_A  + (size_t)p   * 256 + d);
    const float4 e0 = *(const float4*)(g_Pv + (size_t)p   * 256 + d);
    const float4 e1 = *(const float4*)(g_Pv + (size_t)pdn * 256 + d);
    const float4 e2 = *(const float4*)(g_Ph + (size_t)p   * 256 + d);
    const float4 e3 = *(const float4*)(g_Ph + (size_t)prt * 256 + d);
    const float4 s3 = *(const float4*)(g_s3 + d);
    const float4 t3 = *(const float4*)(g_t3 + d);
    const float4 uv = *(const float4*)(g_uv + (size_t)p * 256 + d);
    float w0 = g_wr[0], w1 = g_wr[1], w2 = g_wr[2], w3 = g_wr[3], cr = g_cr;
    float4 o;
#define UR_COMP(f)                                                      \
    {                                                                   \
        float u0 = fmaxf(fmaf(A.f + e0.f, s3.f, t3.f), 0.f);            \
        float u1 = fmaxf(fmaf(A.f + e1.f, s3.f, t3.f), 0.f);            \
        float u2 = fmaxf(fmaf(A.f + e2.f, s3.f, t3.f), 0.f);            \
        float u3 = fmaxf(fmaf(A.f + e3.f, s3.f, t3.f), 0.f);            \
        float rr = fmaxf(w0*u0 + w1*u1 + w2*u2 + w3*u3 + cr, 0.f);      \
        o.f = uv.f * rr;                                                \
    }
    UR_COMP(x) UR_COMP(y) UR_COMP(z) UR_COMP(w)
#undef UR_COMP
    *(uint2*)(g_up + (size_t)p * 256 + d) = pk4(o);
}

// ---------------- HMMA GEMM (mma.sync fp16, 128x128x32, 256 thr) ----------
// PHASE 0, z: 0: xs@wvT -> g_A ; 1: pv@weT -> g_Pv ; 2: ph@weT -> g_Ph ;
//             3: [xs|ag]@vuT -> g_uv (relu s2,t2)
// PHASE 1:    [xs|up]@fcT -> d_out (relu s5,t5), n0 = blockIdx.y*128
static constexpr int STAGE   = 16384;            // 8KB A + 8KB B
static constexpr int OFF_A   = 0;
static constexpr int OFF_B   = 8192;
static constexpr int SMEM_SZ = 3 * STAGE;        // 49152

template<int PHASE>
__global__ __launch_bounds__(256, 1) void mma_gemm(float* __restrict__ OutFc) {
    extern __shared__ char sm[];
    const uint32_t sb = s2u(sm);
    const int tid = threadIdx.x, wid = tid >> 5, lane = tid & 31;
    const int m0 = blockIdx.x * 128, n0 = blockIdx.y * 128;
    const int z = (PHASE == 0) ? (int)blockIdx.z : 4;

    int KT;
    const __half* B_;
    if (PHASE == 0) {
        if (z == 0)      { KT = 512;  B_ = g_wvT; }
        else if (z == 1) { KT = 512;  B_ = g_weT; }
        else if (z == 2) { KT = 512;  B_ = g_weT; }
        else             { KT = 1024; B_ = g_vuT; }
    } else { KT = 768; B_ = g_fcT; }
    const int NIT = KT / 32;

    // per-thread cp.async coords: row = tid>>1 (0..127), chunks cc, cc+1
    const int lrow = tid >> 1;
    const int cc = (tid & 1) * 2;
    const uint32_t so0 = (uint32_t)(lrow * 64 + ((cc ^ ((lrow >> 1) & 3)) << 4));
    const uint32_t so1 = so0 ^ 16;

    auto load_stage = [&](int it) {
        const int k0 = it * 32;
        const uint32_t s = sb + (uint32_t)(it % 3) * STAGE;
        const __half* a_;
        int astr, ak;
        if (PHASE == 0) {
            if (z == 0)      { a_ = g_xs; astr = 512; ak = k0; }
            else if (z == 1) { a_ = g_pv; astr = 512; ak = k0; }
            else if (z == 2) { a_ = g_ph; astr = 512; ak = k0; }
            else {
                if (k0 < 512) { a_ = g_xs; astr = 512; ak = k0; }
                else          { a_ = g_ag; astr = 512; ak = k0 - 512; }
            }
        } else {
            if (k0 < 512) { a_ = g_xs; astr = 512; ak = k0; }
            else          { a_ = g_up; astr = 256; ak = k0 - 512; }
        }
        const __half* ga = a_ + (size_t)(m0 + lrow) * astr + ak + cc * 8;
        cpasync16(s + OFF_A + so0, ga);
        cpasync16(s + OFF_A + so1, ga + 8);
        const __half* gb = B_ + (size_t)(n0 + lrow) * KT + k0 + cc * 8;
        cpasync16(s + OFF_B + so0, gb);
        cpasync16(s + OFF_B + so1, gb + 8);
        CP_COMMIT();
    };

    const int wm = wid >> 2, wn = wid & 3;
    float acc[4][4][4];
    #pragma unroll
    for (int i = 0; i < 4; i++)
        #pragma unroll
        for (int j = 0; j < 4; j++)
            #pragma unroll
            for (int q = 0; q < 4; q++) acc[i][j][q] = 0.f;

    // frag ldsm coords
    const int arow_l = lane & 15;
    const int abump  = lane >> 4;                       // 0/1 -> chunk +0/+1
    const int brow_l = (lane & 7) + ((lane >> 4) << 3); // rows 0-7 / 8-15
    const int bbump  = (lane >> 3) & 1;

    auto compute = [&](int it) {
        const uint32_t s = sb + (uint32_t)(it % 3) * STAGE;
        #pragma unroll
        for (int ks = 0; ks < 2; ks++) {
            const int cb = ks * 2;
            uint32_t ah[4][4], bh[2][4];
            #pragma unroll
            for (int mt = 0; mt < 4; mt++) {
                int rr = wm * 64 + mt * 16 + arow_l;
                int ch = cb + abump;
                uint32_t ad = s + OFF_A + rr * 64 + ((ch ^ ((rr >> 1) & 3)) << 4);
                ldsm4(ah[mt], ad);
            }
            #pragma unroll
            for (int np = 0; np < 2; np++) {
                int rr = wn * 32 + np * 16 + brow_l;
                int ch = cb + bbump;
                uint32_t bd = s + OFF_B + rr * 64 + ((ch ^ ((rr >> 1) & 3)) << 4);
                ldsm4(bh[np], bd);
            }
            #pragma unroll
            for (int mt = 0; mt < 4; mt++)
                #pragma unroll
                for (int nt = 0; nt < 4; nt++)
                    mma16816(acc[mt][nt], ah[mt], &bh[nt >> 1][(nt & 1) * 2]);
        }
    };

    load_stage(0);
    load_stage(1);
    for (int it = 0; it < NIT; it++) {
        if (it < NIT - 1) { CP_WAIT(1); } else { CP_WAIT(0); }
        __syncthreads();
        // issue the next load BEFORE compute: slot (it+2)%3 == (it-1)%3, whose
        // consumers (compute(it-1)) are ordered before us by the barrier above
        if (it + 2 < NIT) load_stage(it + 2);
        compute(it);
    }

    // ---- epilogue ----
    #pragma unroll
    for (int mt = 0; mt < 4; mt++) {
        const int row = m0 + wm * 64 + mt * 16 + (lane >> 2);
        #pragma unroll
        for (int nt = 0; nt < 4; nt++) {
            const int lc = wn * 32 + nt * 8 + (lane & 3) * 2;
            const int gc = n0 + lc;
            float* d = acc[mt][nt];
            if (PHASE == 0 && z < 3) {
                float* Out = (z == 0) ? g_A : (z == 1) ? g_Pv : g_Ph;
                *(float2*)(Out + (size_t)row * 256 + gc)       = make_float2(d[0], d[1]);
                *(float2*)(Out + (size_t)(row + 8) * 256 + gc) = make_float2(d[2], d[3]);
            } else if (PHASE == 0) {
                float s0 = g_s2[gc], s1 = g_s2[gc + 1];
                float t0 = g_t2[gc], t1 = g_t2[gc + 1];
                *(float2*)(g_uv + (size_t)row * 256 + gc) =
                    make_float2(fmaxf(fmaf(d[0], s0, t0), 0.f), fmaxf(fmaf(d[1], s1, t1), 0.f));
                *(float2*)(g_uv + (size_t)(row + 8) * 256 + gc) =
                    make_float2(fmaxf(fmaf(d[2], s0, t0), 0.f), fmaxf(fmaf(d[3], s1, t1), 0.f));
            } else {
                float s0 = g_s5[gc], s1 = g_s5[gc + 1];
                float t0 = g_t5[gc], t1 = g_t5[gc + 1];
                *(float2*)(OutFc + (size_t)row * 512 + gc) =
                    make_float2(fmaxf(fmaf(d[0], s0, t0), 0.f), fmaxf(fmaf(d[1], s1, t1), 0.f));
                *(float2*)(OutFc + (size_t)(row + 8) * 512 + gc) =
                    make_float2(fmaxf(fmaf(d[2], s0, t0), 0.f), fmaxf(fmaf(d[3], s1, t1), 0.f));
            }
        }
    }
}

// ---------------- launch ----------------
extern "C" void kernel_launch(void* const* d_in, const int* in_sizes, int n_in,
                              void* d_out, int out_size) {
    const float* x    = (const float*)d_in[0];
    const float* w_ea = (const float*)d_in[1];
    const float* b_ea = (const float*)d_in[2];
    const float* g1   = (const float*)d_in[3];
    const float* b1   = (const float*)d_in[4];
    const float* m1   = (const float*)d_in[5];
    const float* v1   = (const float*)d_in[6];
    const float* w_vu = (const float*)d_in[7];
    const float* b_vu = (const float*)d_in[8];
    const float* g2   = (const float*)d_in[9];
    const float* b2   = (const float*)d_in[10];
    const float* m2   = (const float*)d_in[11];
    const float* v2   = (const float*)d_in[12];
    const float* w_eu = (const float*)d_in[13];
    const float* b_eu = (const float*)d_in[14];
    const float* g3   = (const float*)d_in[15];
    const float* b3   = (const float*)d_in[16];
    const float* m3   = (const float*)d_in[17];
    const float* v3   = (const float*)d_in[18];
    const float* w_er = (const float*)d_in[19];
    const float* b_er = (const float*)d_in[20];
    const float* g4   = (const float*)d_in[21];
    const float* b4   = (const float*)d_in[22];
    const float* m4   = (const float*)d_in[23];
    const float* v4   = (const float*)d_in[24];
    const float* w_fc = (const float*)d_in[25];
    const float* g5   = (const float*)d_in[26];
    const float* b5   = (const float*)d_in[27];
    const float* m5   = (const float*)d_in[28];
    const float* v5   = (const float*)d_in[29];

    cudaFuncSetAttribute((const void*)mma_gemm<0>,
                         cudaFuncAttributeMaxDynamicSharedMemorySize, SMEM_SZ);
    cudaFuncSetAttribute((const void*)mma_gemm<1>,
                         cudaFuncAttributeMaxDynamicSharedMemorySize, SMEM_SZ);

    prep_all<<<4993, 256>>>(x,
                            w_ea, b_ea, g1, b1, m1, v1,
                            w_vu, b_vu, g2, b2, m2, v2,
                            w_eu, b_eu, g3, b3, m3, v3,
                            w_er, b_er, g4, b4, m4, v4,
                            w_fc, g5, b5, m5, v5);

    mma_gemm<0><<<dim3(64, 2, 4), 256, SMEM_SZ>>>(nullptr);     // g_A,g_Pv,g_Ph,g_uv
    ur_k<<<2048, 256>>>();                                      // -> g_up (fp16)
    mma_gemm<1><<<dim3(64, 4, 1), 256, SMEM_SZ>>>((float*)d_out);
}

// round 11
// speedup vs baseline: 6.9920x; 1.1162x over previous
#include <cuda_runtime.h>
#include <cuda_fp16.h>
#include <cstdint>

#define EPS 1e-3f

static constexpr int MROWS = 8192;   // B*H*W
static constexpr int CCH   = 512;
static constexpr int CH2   = 256;

// ---------------- scratch (device globals; no allocs allowed) ----------------
__device__ __align__(16) float g_A  [MROWS * CH2];
__device__ __align__(16) float g_Pv [MROWS * CH2];
__device__ __align__(16) float g_Ph [MROWS * CH2];
__device__ __align__(16) float g_uv [MROWS * CH2];

__device__ __align__(16) __half g_xs[MROWS * CCH];
__device__ __align__(16) __half g_pv[MROWS * CCH];
__device__ __align__(16) __half g_ph[MROWS * CCH];
__device__ __align__(16) __half g_ag[MROWS * CCH];
__device__ __align__(16) __half g_up[MROWS * CH2];

__device__ __align__(16) __half g_vuT[256 * 1024];
__device__ __align__(16) __half g_wvT[256 *  512];
__device__ __align__(16) __half g_weT[256 *  512];
__device__ __align__(16) __half g_fcT[512 *  768];

__device__ __align__(16) float g_s2[CH2], g_t2[CH2], g_s3[CH2], g_t3[CH2];
__device__ __align__(16) float g_s5[CCH], g_t5[CCH];
__device__ float g_wr[4], g_cr;

// ---------------- PTX helpers ----------------
__device__ __forceinline__ uint32_t s2u(const void* p) {
    uint32_t a;
    asm("{ .reg .u64 t; cvta.to.shared.u64 t, %1; cvt.u32.u64 %0, t; }" : "=r"(a) : "l"(p));
    return a;
}
__device__ __forceinline__ void cpasync16(uint32_t s, const void* g) {
    asm volatile("cp.async.cg.shared.global [%0], [%1], 16;" :: "r"(s), "l"(g));
}
#define CP_COMMIT() asm volatile("cp.async.commit_group;" ::: "memory")
#define CP_WAIT(n)  asm volatile("cp.async.wait_group %0;" :: "n"(n) : "memory")

__device__ __forceinline__ void ldsm4(uint32_t* r, uint32_t addr) {
    asm volatile("ldmatrix.sync.aligned.m8n8.x4.shared.b16 {%0,%1,%2,%3}, [%4];"
                 : "=r"(r[0]), "=r"(r[1]), "=r"(r[2]), "=r"(r[3]) : "r"(addr));
}
__device__ __forceinline__ void mma16816(float* d, const uint32_t* a, const uint32_t* b) {
    asm volatile(
        "mma.sync.aligned.m16n8k16.row.col.f32.f16.f16.f32 "
        "{%0,%1,%2,%3}, {%4,%5,%6,%7}, {%8,%9}, {%0,%1,%2,%3};"
        : "+f"(d[0]), "+f"(d[1]), "+f"(d[2]), "+f"(d[3])
        : "r"(a[0]), "r"(a[1]), "r"(a[2]), "r"(a[3]), "r"(b[0]), "r"(b[1]));
}

// pack float4 -> 4x fp16 (uint2) — bit-cast intrinsics only, no address-of locals
__device__ __forceinline__ uint2 pk4(float4 v) {
    uint2 r;
    r.x = (uint32_t)__half_as_ushort(__float2half_rn(v.x)) |
          ((uint32_t)__half_as_ushort(__float2half_rn(v.y)) << 16);
    r.y = (uint32_t)__half_as_ushort(__float2half_rn(v.z)) |
          ((uint32_t)__half_as_ushort(__float2half_rn(v.w)) << 16);
    return r;
}

// ---------------- fused prologue: aggsplit + 4x weight transpose + fold ---------
template<int W>
__device__ __forceinline__ void prepw_body(const float* __restrict__ src,
                                           float (*t)[33], int bi, int tid) {
    constexpr int K = (W == 0) ? 1024 : ((W == 3) ? 768 : 512);
    constexpr int N = (W == 3) ? 512 : 256;
    constexpr int KB = K / 32;
    __half* dst = (W == 0) ? g_vuT : (W == 1) ? g_wvT : (W == 2) ? g_weT : g_fcT;
    const int k0 = (bi % KB) * 32, n0 = (bi / KB) * 32;
    const int r = tid >> 5, c = tid & 31;   // 8 x 32
    #pragma unroll
    for (int i = 0; i < 4; i++)
        t[r + 8 * i][c] = src[(size_t)(k0 + r + 8 * i) * N + n0 + c];
    __syncthreads();
    #pragma unroll
    for (int i = 0; i < 4; i++)
        dst[(size_t)(n0 + r + 8 * i) * K + k0 + c] = __float2half_rn(t[c][r + 8 * i]);
}

__global__ __launch_bounds__(256) void prep_all(
    const float* __restrict__ X,
    const float* w_ea, const float* b_ea,
    const float* g1, const float* b1, const float* m1, const float* v1,
    const float* w_vu, const float* b_vu,
    const float* g2, const float* b2, const float* m2, const float* v2,
    const float* w_eu, const float* b_eu,
    const float* g3, const float* b3, const float* m3, const float* v3,
    const float* w_er, const float* b_er,
    const float* g4, const float* b4, const float* m4, const float* v4,
    const float* w_fc,
    const float* g5, const float* b5, const float* m5, const float* v5) {
    __shared__ float t[32][33];
    const int b = blockIdx.x, tid = threadIdx.x;

    if (b < 4096) {
        float s1 = g1[0] * rsqrtf(v1[0] + EPS);
        float w0 = w_ea[0] * s1, w1 = w_ea[1] * s1, w2 = w_ea[2] * s1, w3 = w_ea[3] * s1;
        float ca = (b_ea[0] - m1[0]) * s1 + b1[0];

        int idx = b * 256 + tid;
        int p = idx >> 7;
        int c = (idx & 127) << 2;
        int h = (p >> 6) & 63, w = p & 63;
        int baseH = p & ~4032;
        int pu = baseH | (((h + 63) & 63) << 6);
        int pd = baseH | (((h + 1) & 63) << 6);
        int baseW = p & ~63;
        int pl = baseW | ((w + 63) & 63);
        int pr = baseW | ((w + 1) & 63);
        float4 xv = *(const float4*)(X + (size_t)p  * 512 + c);
        float4 xu = *(const float4*)(X + (size_t)pu * 512 + c);
        float4 xd = *(const float4*)(X + (size_t)pd * 512 + c);
        float4 xl = *(const float4*)(X + (size_t)pl * 512 + c);
        float4 xr = *(const float4*)(X + (size_t)pr * 512 + c);
        float4 ag, pv, ph;
        ag.x = fmaxf(fmaf(xv.x, w0 * xu.x + w1 * xd.x + w2 * xl.x + w3 * xr.x, ca), 0.f);
        ag.y = fmaxf(fmaf(xv.y, w0 * xu.y + w1 * xd.y + w2 * xl.y + w3 * xr.y, ca), 0.f);
        ag.z = fmaxf(fmaf(xv.z, w0 * xu.z + w1 * xd.z + w2 * xl.z + w3 * xr.z, ca), 0.f);
        ag.w = fmaxf(fmaf(xv.w, w0 * xu.w + w1 * xd.w + w2 * xl.w + w3 * xr.w, ca), 0.f);
        pv = make_float4(xv.x * xu.x, xv.y * xu.y, xv.z * xu.z, xv.w * xu.w);
        ph = make_float4(xv.x * xl.x, xv.y * xl.y, xv.z * xl.z, xv.w * xl.w);

        size_t o = (size_t)p * 512 + c;
        *(uint2*)(g_xs + o) = pk4(xv);
        *(uint2*)(g_pv + o) = pk4(pv);
        *(uint2*)(g_ph + o) = pk4(ph);
        *(uint2*)(g_ag + o) = pk4(ag);
    } else if (b < 4352) {
        prepw_body<0>(w_vu, t, b - 4096, tid);
    } else if (b < 4480) {
        prepw_body<1>(w_eu, t, b - 4352, tid);
    } else if (b < 4608) {
        prepw_body<2>(w_eu + 512 * 256, t, b - 4480, tid);
    } else if (b < 4992) {
        prepw_body<3>(w_fc, t, b - 4608, tid);
    } else {
        int d = tid;
        if (d < CH2) {
            float s2 = g2[d] * rsqrtf(v2[d] + EPS);
            g_s2[d] = s2;
            g_t2[d] = (b_vu[d] - m2[d]) * s2 + b2[d];
            float s3 = g3[d] * rsqrtf(v3[d] + EPS);
            g_s3[d] = s3;
            g_t3[d] = (b_eu[d] - m3[d]) * s3 + b3[d];
        }
        #pragma unroll
        for (int dd = d; dd < CCH; dd += 256) {
            float s5 = g5[dd] * rsqrtf(v5[dd] + EPS);
            g_s5[dd] = s5;
            g_t5[dd] = b5[dd] - m5[dd] * s5;
        }
        if (d == 0) {
            float s4 = g4[0] * rsqrtf(v4[0] + EPS);
            #pragma unroll
            for (int n = 0; n < 4; n++) g_wr[n] = w_er[n] * s4;
            g_cr = (b_er[0] - m4[0]) * s4 + b4[0];
        }
    }
}

// ---------------- edge reduce + vertex*edge product (-> fp16 upd) ----------------
__global__ void ur_k() {
    int idx = blockIdx.x * 256 + threadIdx.x;   // over 8192*64 float4s
    int p = idx >> 6;
    int d = (idx & 63) << 2;
    int h = (p >> 6) & 63, w = p & 63;
    int pdn = (p & ~4032) | (((h + 1) & 63) << 6);
    int prt = (p & ~63)   | ((w + 1) & 63);
    const float4 A  = *(const float4*)(g_A  + (size_t)p   * 256 + d);
    const float4 e0 = *(const float4*)(g_Pv + (size_t)p   * 256 + d);
    const float4 e1 = *(const float4*)(g_Pv + (size_t)pdn * 256 + d);
    const float4 e2 = *(const float4*)(g_Ph + (size_t)p   * 256 + d);
    const float4 e3 = *(const float4*)(g_Ph + (size_t)prt * 256 + d);
    const float4 s3 = *(const float4*)(g_s3 + d);
    const float4 t3 = *(const float4*)(g_t3 + d);
    const float4 uv = *(const float4*)(g_uv + (size_t)p * 256 + d);
    float w0 = g_wr[0], w1 = g_wr[1], w2 = g_wr[2], w3 = g_wr[3], cr = g_cr;
    float4 o;
#define UR_COMP(f)                                                      \
    {                                                                   \
        float u0 = fmaxf(fmaf(A.f + e0.f, s3.f, t3.f), 0.f);            \
        float u1 = fmaxf(fmaf(A.f + e1.f, s3.f, t3.f), 0.f);            \
        float u2 = fmaxf(fmaf(A.f + e2.f, s3.f, t3.f), 0.f);            \
        float u3 = fmaxf(fmaf(A.f + e3.f, s3.f, t3.f), 0.f);            \
        float rr = fmaxf(w0*u0 + w1*u1 + w2*u2 + w3*u3 + cr, 0.f);      \
        o.f = uv.f * rr;                                                \
    }
    UR_COMP(x) UR_COMP(y) UR_COMP(z) UR_COMP(w)
#undef UR_COMP
    *(uint2*)(g_up + (size_t)p * 256 + d) = pk4(o);
}

// ---------------- HMMA GEMM (mma.sync fp16, 128x128x32, 512 thr) ----------
// 16 warps (4x4), each owns a 32x32 sub-tile -> 32 accum regs/thread.
// PHASE 0, z: 0: xs@wvT -> g_A ; 1: pv@weT -> g_Pv ; 2: ph@weT -> g_Ph ;
//             3: [xs|ag]@vuT -> g_uv (relu s2,t2)
// PHASE 1:    [xs|up]@fcT -> d_out (relu s5,t5), n0 = blockIdx.y*128
static constexpr int STAGE   = 16384;            // 8KB A + 8KB B
static constexpr int OFF_A   = 0;
static constexpr int OFF_B   = 8192;
static constexpr int SMEM_SZ = 3 * STAGE;        // 49152

template<int PHASE>
__global__ __launch_bounds__(512, 1) void mma_gemm(float* __restrict__ OutFc) {
    extern __shared__ char sm[];
    const uint32_t sb = s2u(sm);
    const int tid = threadIdx.x, wid = tid >> 5, lane = tid & 31;
    const int m0 = blockIdx.x * 128, n0 = blockIdx.y * 128;
    const int z = (PHASE == 0) ? (int)blockIdx.z : 4;

    int KT;
    const __half* B_;
    if (PHASE == 0) {
        if (z == 0)      { KT = 512;  B_ = g_wvT; }
        else if (z == 1) { KT = 512;  B_ = g_weT; }
        else if (z == 2) { KT = 512;  B_ = g_weT; }
        else             { KT = 1024; B_ = g_vuT; }
    } else { KT = 768; B_ = g_fcT; }
    const int NIT = KT / 32;

    // per-thread cp.async coords: row = tid>>2 (0..127), chunk cc = tid&3
    const int lrow = tid >> 2;
    const int cc = tid & 3;
    const uint32_t so0 = (uint32_t)(lrow * 64 + ((cc ^ ((lrow >> 1) & 3)) << 4));

    auto load_stage = [&](int it) {
        const int k0 = it * 32;
        const uint32_t s = sb + (uint32_t)(it % 3) * STAGE;
        const __half* a_;
        int astr, ak;
        if (PHASE == 0) {
            if (z == 0)      { a_ = g_xs; astr = 512; ak = k0; }
            else if (z == 1) { a_ = g_pv; astr = 512; ak = k0; }
            else if (z == 2) { a_ = g_ph; astr = 512; ak = k0; }
            else {
                if (k0 < 512) { a_ = g_xs; astr = 512; ak = k0; }
                else          { a_ = g_ag; astr = 512; ak = k0 - 512; }
            }
        } else {
            if (k0 < 512) { a_ = g_xs; astr = 512; ak = k0; }
            else          { a_ = g_up; astr = 256; ak = k0 - 512; }
        }
        cpasync16(s + OFF_A + so0, a_ + (size_t)(m0 + lrow) * astr + ak + cc * 8);
        cpasync16(s + OFF_B + so0, B_ + (size_t)(n0 + lrow) * KT + k0 + cc * 8);
        CP_COMMIT();
    };

    const int wm = wid >> 2, wn = wid & 3;        // 4x4 warp grid, 32x32 each
    float acc[2][4][4];
    #pragma unroll
    for (int i = 0; i < 2; i++)
        #pragma unroll
        for (int j = 0; j < 4; j++)
            #pragma unroll
            for (int q = 0; q < 4; q++) acc[i][j][q] = 0.f;

    // frag ldsm coords
    const int arow_l = lane & 15;
    const int abump  = lane >> 4;                       // 0/1 -> chunk +0/+1
    const int brow_l = (lane & 7) + ((lane >> 4) << 3); // rows 0-7 / 8-15
    const int bbump  = (lane >> 3) & 1;

    auto compute = [&](int it) {
        const uint32_t s = sb + (uint32_t)(it % 3) * STAGE;
        #pragma unroll
        for (int ks = 0; ks < 2; ks++) {
            const int cb = ks * 2;
            uint32_t ah[2][4], bh[2][4];
            #pragma unroll
            for (int mt = 0; mt < 2; mt++) {
                int rr = wm * 32 + mt * 16 + arow_l;
                int ch = cb + abump;
                uint32_t ad = s + OFF_A + rr * 64 + ((ch ^ ((rr >> 1) & 3)) << 4);
                ldsm4(ah[mt], ad);
            }
            #pragma unroll
            for (int np = 0; np < 2; np++) {
                int rr = wn * 32 + np * 16 + brow_l;
                int ch = cb + bbump;
                uint32_t bd = s + OFF_B + rr * 64 + ((ch ^ ((rr >> 1) & 3)) << 4);
                ldsm4(bh[np], bd);
            }
            #pragma unroll
            for (int mt = 0; mt < 2; mt++)
                #pragma unroll
                for (int nt = 0; nt < 4; nt++)
                    mma16816(acc[mt][nt], ah[mt], &bh[nt >> 1][(nt & 1) * 2]);
        }
    };

    load_stage(0);
    load_stage(1);
    for (int it = 0; it < NIT; it++) {
        if (it < NIT - 1) { CP_WAIT(1); } else { CP_WAIT(0); }
        __syncthreads();
        // issue the next load BEFORE compute: slot (it+2)%3 == (it-1)%3, whose
        // consumers (compute(it-1)) are ordered before us by the barrier above
        if (it + 2 < NIT) load_stage(it + 2);
        compute(it);
    }

    // ---- epilogue ----
    #pragma unroll
    for (int mt = 0; mt < 2; mt++) {
        const int row = m0 + wm * 32 + mt * 16 + (lane >> 2);
        #pragma unroll
        for (int nt = 0; nt < 4; nt++) {
            const int lc = wn * 32 + nt * 8 + (lane & 3) * 2;
            const int gc = n0 + lc;
            float* d = acc[mt][nt];
            if (PHASE == 0 && z < 3) {
                float* Out = (z == 0) ? g_A : (z == 1) ? g_Pv : g_Ph;
                *(float2*)(Out + (size_t)row * 256 + gc)       = make_float2(d[0], d[1]);
                *(float2*)(Out + (size_t)(row + 8) * 256 + gc) = make_float2(d[2], d[3]);
            } else if (PHASE == 0) {
                float s0 = g_s2[gc], s1 = g_s2[gc + 1];
                float t0 = g_t2[gc], t1 = g_t2[gc + 1];
                *(float2*)(g_uv + (size_t)row * 256 + gc) =
                    make_float2(fmaxf(fmaf(d[0], s0, t0), 0.f), fmaxf(fmaf(d[1], s1, t1), 0.f));
                *(float2*)(g_uv + (size_t)(row + 8) * 256 + gc) =
                    make_float2(fmaxf(fmaf(d[2], s0, t0), 0.f), fmaxf(fmaf(d[3], s1, t1), 0.f));
            } else {
                float s0 = g_s5[gc], s1 = g_s5[gc + 1];
                float t0 = g_t5[gc], t1 = g_t5[gc + 1];
                *(float2*)(OutFc + (size_t)row * 512 + gc) =
                    make_float2(fmaxf(fmaf(d[0], s0, t0), 0.f), fmaxf(fmaf(d[1], s1, t1), 0.f));
                *(float2*)(OutFc + (size_t)(row + 8) * 512 + gc) =
                    make_float2(fmaxf(fmaf(d[2], s0, t0), 0.f), fmaxf(fmaf(d[3], s1, t1), 0.f));
            }
        }
    }
}

// ---------------- launch ----------------
extern "C" void kernel_launch(void* const* d_in, const int* in_sizes, int n_in,
                              void* d_out, int out_size) {
    const float* x    = (const float*)d_in[0];
    const float* w_ea = (const float*)d_in[1];
    const float* b_ea = (const float*)d_in[2];
    const float* g1   = (const float*)d_in[3];
    const float* b1   = (const float*)d_in[4];
    const float* m1   = (const float*)d_in[5];
    const float* v1   = (const float*)d_in[6];
    const float* w_vu = (const float*)d_in[7];
    const float* b_vu = (const float*)d_in[8];
    const float* g2   = (const float*)d_in[9];
    const float* b2   = (const float*)d_in[10];
    const float* m2   = (const float*)d_in[11];
    const float* v2   = (const float*)d_in[12];
    const float* w_eu = (const float*)d_in[13];
    const float* b_eu = (const float*)d_in[14];
    const float* g3   = (const float*)d_in[15];
    const float* b3   = (const float*)d_in[16];
    const float* m3   = (const float*)d_in[17];
    const float* v3   = (const float*)d_in[18];
    const float* w_er = (const float*)d_in[19];
    const float* b_er = (const float*)d_in[20];
    const float* g4   = (const float*)d_in[21];
    const float* b4   = (const float*)d_in[22];
    const float* m4   = (const float*)d_in[23];
    const float* v4   = (const float*)d_in[24];
    const float* w_fc = (const float*)d_in[25];
    const float* g5   = (const float*)d_in[26];
    const float* b5   = (const float*)d_in[27];
    const float* m5   = (const float*)d_in[28];
    const float* v5   = (const float*)d_in[29];

    cudaFuncSetAttribute((const void*)mma_gemm<0>,
                         cudaFuncAttributeMaxDynamicSharedMemorySize, SMEM_SZ);
    cudaFuncSetAttribute((const void*)mma_gemm<1>,
                         cudaFuncAttributeMaxDynamicSharedMemorySize, SMEM_SZ);

    prep_all<<<4993, 256>>>(x,
                            w_ea, b_ea, g1, b1, m1, v1,
                            w_vu, b_vu, g2, b2, m2, v2,
                            w_eu, b_eu, g3, b3, m3, v3,
                            w_er, b_er, g4, b4, m4, v4,
                            w_fc, g5, b5, m5, v5);

    // tile is 128x128 regardless of thread count: grid.y = N/128
    mma_gemm<0><<<dim3(64, 2, 4), 512, SMEM_SZ>>>(nullptr);     // g_A,g_Pv,g_Ph,g_uv
    ur_k<<<2048, 256>>>();                                      // -> g_up (fp16)
    mma_gemm<1><<<dim3(64, 4, 1), 512, SMEM_SZ>>>((float*)d_out);
}